// round 1
// baseline (speedup 1.0000x reference)
#include <cuda_runtime.h>
#include <math.h>

#define N_NODES  50000
#define N_EDGES  600000
#define NF       128
#define N_GRAPHS 256
#define DIM      95
#define N_OUT    12
#define N_ITERS  10
#define BN_EPS   1e-5f

// ---------------- scratch (no allocs allowed) ----------------
__device__ float g_hin[N_NODES * NF];     // x + agg
__device__ float g_t1[N_NODES * NF];      // relu((x+agg)@W1a + b1a)
__device__ float g_x1[N_NODES * NF];      // relu(t1@W1b + b1b)
__device__ int   g_counts[N_NODES];
__device__ int   g_offsets[N_NODES + 1];
__device__ int   g_cursor[N_NODES];
__device__ int   g_srcidx[N_EDGES];
__device__ float g_stats[2 * NF];         // [sum, sumsq] per feature
__device__ float g_xg[N_GRAPHS * NF];
__device__ float g_h0[N_GRAPHS * NF];
__device__ float g_h1[N_GRAPHS * NF];
__device__ int   g_is64;

// ---------------- dtype probe (int64 vs int32 indices) ----------------
// If data is int64, every odd int32 word (the high half) of the first 1024
// entries is 0 (values are small non-negative). If int32, those words are
// real indices and are ~never all zero.
__global__ void detect_kernel(const int* ei32) {
    int bad = 0;
    for (int i = threadIdx.x; i < 1024; i += 32)
        if (ei32[2 * i + 1] != 0) bad = 1;
    unsigned m = __ballot_sync(0xffffffffu, bad);
    if (threadIdx.x == 0) g_is64 = (m == 0) ? 1 : 0;
}

__device__ __forceinline__ int load_index(const void* p, long long i, int is64) {
    if (is64) return (int)((const long long*)p)[i];
    return ((const int*)p)[i];
}

// ---------------- init ----------------
__global__ void init_kernel() {
    int i = blockIdx.x * blockDim.x + threadIdx.x;
    if (i < N_NODES) g_counts[i] = 0;
    if (i < 2 * NF) g_stats[i] = 0.0f;
}

// ---------------- CSR build ----------------
__global__ void count_kernel(const void* ei) {
    int is64 = g_is64;
    for (int e = blockIdx.x * blockDim.x + threadIdx.x; e < N_EDGES;
         e += gridDim.x * blockDim.x) {
        int d = load_index(ei, (long long)N_EDGES + e, is64);
        atomicAdd(&g_counts[d], 1);
    }
}

// single-block chunked exclusive scan over g_counts -> g_offsets/g_cursor
__global__ void scan_kernel() {
    __shared__ int sm[1024];
    int t = threadIdx.x;
    const int CH = (N_NODES + 1023) / 1024;   // 49
    int start = t * CH;
    int s = 0;
    for (int i = 0; i < CH; i++) {
        int idx = start + i;
        if (idx < N_NODES) s += g_counts[idx];
    }
    sm[t] = s;
    __syncthreads();
    for (int off = 1; off < 1024; off <<= 1) {
        int v = (t >= off) ? sm[t - off] : 0;
        __syncthreads();
        sm[t] += v;
        __syncthreads();
    }
    int run = sm[t] - s;  // exclusive prefix of this thread's chunk
    for (int i = 0; i < CH; i++) {
        int idx = start + i;
        if (idx < N_NODES) {
            g_offsets[idx] = run;
            g_cursor[idx] = run;
            run += g_counts[idx];
        }
    }
    if (t == 1023) g_offsets[N_NODES] = run;
}

__global__ void scatter_kernel(const void* ei) {
    int is64 = g_is64;
    for (int e = blockIdx.x * blockDim.x + threadIdx.x; e < N_EDGES;
         e += gridDim.x * blockDim.x) {
        int s = load_index(ei, e, is64);
        int d = load_index(ei, (long long)N_EDGES + e, is64);
        int pos = atomicAdd(&g_cursor[d], 1);
        g_srcidx[pos] = s;
    }
}

// ---------------- GIN aggregation: h = x + sum_{j->i} x_j ----------------
// one warp per node; each lane owns one float4 (4 features)
__global__ void agg_kernel(const float4* __restrict__ x4) {
    int node = blockIdx.x * 8 + (threadIdx.x >> 5);
    int lane = threadIdx.x & 31;
    if (node >= N_NODES) return;
    float4 acc = x4[node * 32 + lane];
    int e0 = g_offsets[node];
    int e1 = g_offsets[node + 1];
    for (int e = e0; e < e1; e++) {
        int s = g_srcidx[e];
        float4 v = x4[s * 32 + lane];
        acc.x += v.x; acc.y += v.y; acc.z += v.z; acc.w += v.w;
    }
    ((float4*)g_hin)[node * 32 + lane] = acc;
}

// ---------------- GEMM: out = relu(A[M,128] @ W[128,128] + b) ----------------
// block: 256 threads, tile 128 rows x 128 cols, 8x8 register tile per thread
__global__ void gemm_relu_kernel(const float* __restrict__ A,
                                 const float* __restrict__ W,
                                 const float* __restrict__ bias,
                                 float* __restrict__ out, int M) {
    extern __shared__ float smm[];
    float* As = smm;                         // [128][132] (padded)
    float* Ws = smm + 128 * 132;             // [128][128]
    float* bs = smm + 128 * 132 + 128 * 128; // [128]
    int t = threadIdx.x;
    int row0 = blockIdx.x * 128;

    const float4* W4 = (const float4*)W;
    float4* Ws4 = (float4*)Ws;
#pragma unroll
    for (int i = t; i < 4096; i += 256) Ws4[i] = W4[i];
    if (t < 128) bs[t] = bias[t];

    const float4* A4 = (const float4*)A;
    for (int i = t; i < 4096; i += 256) {
        int r = i >> 5;
        int c4 = i & 31;
        int gr = row0 + r;
        float4 v = (gr < M) ? A4[(long long)gr * 32 + c4] : make_float4(0.f, 0.f, 0.f, 0.f);
        *(float4*)&As[r * 132 + c4 * 4] = v;
    }
    __syncthreads();

    int tx = t & 15;   // col group: 8 cols
    int ty = t >> 4;   // row group: 8 rows
    float acc[8][8];
#pragma unroll
    for (int i = 0; i < 8; i++)
#pragma unroll
        for (int j = 0; j < 8; j++) acc[i][j] = 0.0f;

#pragma unroll 4
    for (int k = 0; k < 128; k++) {
        float a[8], w[8];
#pragma unroll
        for (int i = 0; i < 8; i++) a[i] = As[(ty * 8 + i) * 132 + k];
        float4 w0 = *(const float4*)&Ws[k * 128 + tx * 8];
        float4 w1 = *(const float4*)&Ws[k * 128 + tx * 8 + 4];
        w[0] = w0.x; w[1] = w0.y; w[2] = w0.z; w[3] = w0.w;
        w[4] = w1.x; w[5] = w1.y; w[6] = w1.z; w[7] = w1.w;
#pragma unroll
        for (int i = 0; i < 8; i++)
#pragma unroll
            for (int j = 0; j < 8; j++) acc[i][j] += a[i] * w[j];
    }

#pragma unroll
    for (int i = 0; i < 8; i++) {
        int gr = row0 + ty * 8 + i;
        if (gr < M) {
            float4 o0, o1;
            o0.x = fmaxf(acc[i][0] + bs[tx * 8 + 0], 0.f);
            o0.y = fmaxf(acc[i][1] + bs[tx * 8 + 1], 0.f);
            o0.z = fmaxf(acc[i][2] + bs[tx * 8 + 2], 0.f);
            o0.w = fmaxf(acc[i][3] + bs[tx * 8 + 3], 0.f);
            o1.x = fmaxf(acc[i][4] + bs[tx * 8 + 4], 0.f);
            o1.y = fmaxf(acc[i][5] + bs[tx * 8 + 5], 0.f);
            o1.z = fmaxf(acc[i][6] + bs[tx * 8 + 6], 0.f);
            o1.w = fmaxf(acc[i][7] + bs[tx * 8 + 7], 0.f);
            *(float4*)&out[(long long)gr * 128 + tx * 8] = o0;
            *(float4*)&out[(long long)gr * 128 + tx * 8 + 4] = o1;
        }
    }
}

// ---------------- batchnorm statistics ----------------
__global__ void bnstat_kernel() {
    int f = threadIdx.x;   // 128 threads
    float s = 0.f, sq = 0.f;
    for (int r = blockIdx.x; r < N_NODES; r += gridDim.x) {
        float v = g_x1[(long long)r * NF + f];
        s += v;
        sq += v * v;
    }
    atomicAdd(&g_stats[f], s);
    atomicAdd(&g_stats[NF + f], sq);
}

// ---------------- pooling + BN affine (BN is linear -> fold after mean) ----
__global__ void pool_kernel(const void* batch, const float* __restrict__ gamma,
                            const float* __restrict__ beta) {
    int g = blockIdx.x;
    int f = threadIdx.x;
    int is64 = g_is64;
    __shared__ int se[2];
    if (f < 2) {
        int target = g + f;  // lower_bound(g) and lower_bound(g+1)
        int lo = 0, hi = N_NODES;
        while (lo < hi) {
            int mid = (lo + hi) >> 1;
            int b = load_index(batch, mid, is64);
            if (b < target) lo = mid + 1; else hi = mid;
        }
        se[f] = lo;
    }
    __syncthreads();
    int s = se[0], e = se[1];
    float sum = 0.f;
    for (int r = s; r < e; r++) sum += g_x1[(long long)r * NF + f];
    float mu = g_stats[f] / (float)N_NODES;
    float var = g_stats[NF + f] / (float)N_NODES - mu * mu;
    float val = 0.f;
    if (e > s) {
        float m = sum / (float)(e - s);
        val = gamma[f] * (m - mu) * rsqrtf(var + BN_EPS) + beta[f];
    }
    g_xg[g * NF + f] = val;
    g_h0[g * NF + f] = val;   // h init = xg
}

// ---------------- recurrent gated iteration ----------------
// h_new = [tanh(cat@Wl2+bl2), sigmoid(cat@Wl1+bl1)], cat = [xg, h]
// 64 blocks x 128 threads; each block does 4 graph rows; thread = output col
__global__ void recur_kernel(const float* __restrict__ Wl1, const float* __restrict__ bl1,
                             const float* __restrict__ Wl2, const float* __restrict__ bl2,
                             int flip) {
    const float* hin = flip ? g_h1 : g_h0;
    float* hout = flip ? g_h0 : g_h1;
    int g0 = blockIdx.x * 4;
    int t = threadIdx.x;
    __shared__ float cat[4][256];
#pragma unroll
    for (int r = 0; r < 4; r++) {
        cat[r][t] = g_xg[(g0 + r) * NF + t];
        cat[r][NF + t] = hin[(g0 + r) * NF + t];
    }
    __syncthreads();

    const float* Wc;
    float bias;
    if (t < 64) { Wc = Wl2 + t; bias = bl2[t]; }
    else        { Wc = Wl1 + (t - 64); bias = bl1[t - 64]; }

    float a0 = bias, a1 = bias, a2 = bias, a3 = bias;
#pragma unroll 8
    for (int k = 0; k < 256; k++) {
        float w = Wc[k * 64];
        a0 += cat[0][k] * w;
        a1 += cat[1][k] * w;
        a2 += cat[2][k] * w;
        a3 += cat[3][k] * w;
    }
    float o[4] = {a0, a1, a2, a3};
#pragma unroll
    for (int r = 0; r < 4; r++) {
        float v = (t < 64) ? tanhf(o[r]) : (1.0f / (1.0f + expf(-o[r])));
        hout[(g0 + r) * NF + t] = v;
    }
}

// ---------------- output MLP ----------------
__global__ void mlp_kernel(const float* __restrict__ Wm1, const float* __restrict__ bm1,
                           const float* __restrict__ Wm2, const float* __restrict__ bm2,
                           float* __restrict__ out) {
    int g = blockIdx.x;
    int t = threadIdx.x;   // 128
    __shared__ float hrow[NF];
    __shared__ float hid[DIM];
    hrow[t] = g_h0[g * NF + t];
    __syncthreads();
    if (t < DIM) {
        float a = bm1[t];
#pragma unroll 8
        for (int k = 0; k < NF; k++) a += hrow[k] * Wm1[k * DIM + t];
        hid[t] = fmaxf(a, 0.f);
    }
    __syncthreads();
    if (t < N_OUT) {
        float a = bm2[t];
        for (int k = 0; k < DIM; k++) a += hid[k] * Wm2[k * N_OUT + t];
        out[g * N_OUT + t] = a;
    }
}

// ---------------- host ----------------
extern "C" void kernel_launch(void* const* d_in, const int* in_sizes, int n_in,
                              void* d_out, int out_size) {
    const float* x     = (const float*)d_in[0];
    const void*  ei    = d_in[1];
    const void*  batch = d_in[2];
    const float* W1a = (const float*)d_in[3];
    const float* b1a = (const float*)d_in[4];
    const float* W1b = (const float*)d_in[5];
    const float* b1b = (const float*)d_in[6];
    const float* gamma = (const float*)d_in[7];
    const float* beta  = (const float*)d_in[8];
    const float* Wl1 = (const float*)d_in[9];
    const float* bl1 = (const float*)d_in[10];
    const float* Wl2 = (const float*)d_in[11];
    const float* bl2 = (const float*)d_in[12];
    const float* Wm1 = (const float*)d_in[13];
    const float* bm1 = (const float*)d_in[14];
    const float* Wm2 = (const float*)d_in[15];
    const float* bm2 = (const float*)d_in[16];
    float* out = (float*)d_out;

    void *p_hin, *p_t1, *p_x1;
    cudaGetSymbolAddress(&p_hin, g_hin);
    cudaGetSymbolAddress(&p_t1, g_t1);
    cudaGetSymbolAddress(&p_x1, g_x1);

    const int SMEM = (128 * 132 + 128 * 128 + 128) * (int)sizeof(float);  // 133632 B
    cudaFuncSetAttribute(gemm_relu_kernel,
                         cudaFuncAttributeMaxDynamicSharedMemorySize, SMEM);

    detect_kernel<<<1, 32>>>((const int*)ei);
    init_kernel<<<(N_NODES + 255) / 256, 256>>>();
    count_kernel<<<1024, 256>>>(ei);
    scan_kernel<<<1, 1024>>>();
    scatter_kernel<<<1024, 256>>>(ei);
    agg_kernel<<<(N_NODES + 7) / 8, 256>>>((const float4*)x);
    gemm_relu_kernel<<<(N_NODES + 127) / 128, 256, SMEM>>>(
        (const float*)p_hin, W1a, b1a, (float*)p_t1, N_NODES);
    gemm_relu_kernel<<<(N_NODES + 127) / 128, 256, SMEM>>>(
        (const float*)p_t1, W1b, b1b, (float*)p_x1, N_NODES);
    bnstat_kernel<<<512, 128>>>();
    pool_kernel<<<N_GRAPHS, 128>>>(batch, gamma, beta);
    for (int it = 0; it < N_ITERS; it++)
        recur_kernel<<<N_GRAPHS / 4, 128>>>(Wl1, bl1, Wl2, bl2, it & 1);
    mlp_kernel<<<N_GRAPHS, 128>>>(Wm1, bm1, Wm2, bm2, out);
}

// round 2
// speedup vs baseline: 1.7448x; 1.7448x over previous
#include <cuda_runtime.h>
#include <math.h>

#define N_NODES  50000
#define N_EDGES  600000
#define NF       128
#define N_GRAPHS 256
#define DIM      95
#define N_OUT    12
#define N_ITERS  10
#define BN_EPS   1e-5f
#define SCAN_NBLK 196            // ceil(50000/256)

// ---------------- scratch (no allocs allowed) ----------------
__device__ float g_hin[N_NODES * NF];     // x + agg
__device__ float g_t1[N_NODES * NF];      // relu((x+agg)@W1a + b1a)
__device__ float g_x1[N_NODES * NF];      // relu(t1@W1b + b1b)
__device__ int   g_counts[N_NODES];
__device__ int   g_offsets[N_NODES + 1];
__device__ int   g_cursor[N_NODES];
__device__ int   g_srcidx[N_EDGES];
__device__ int   g_bsums[SCAN_NBLK];
__device__ int   g_bpre[SCAN_NBLK];
__device__ float g_stats[2 * NF];         // [sum(128), sumsq(128)]
__device__ float g_xg[N_GRAPHS * NF];
__device__ float g_h0[N_GRAPHS * NF];
__device__ int   g_is64;

// ---------------- dtype probe (int64 vs int32 indices) ----------------
__global__ void detect_kernel(const int* ei32) {
    int bad = 0;
    for (int i = threadIdx.x; i < 1024; i += 32)
        if (ei32[2 * i + 1] != 0) bad = 1;
    unsigned m = __ballot_sync(0xffffffffu, bad);
    if (threadIdx.x == 0) g_is64 = (m == 0) ? 1 : 0;
}

__device__ __forceinline__ int load_index(const void* p, long long i, int is64) {
    if (is64) return (int)((const long long*)p)[i];
    return ((const int*)p)[i];
}

// ---------------- init ----------------
__global__ void init_kernel() {
    int i = blockIdx.x * blockDim.x + threadIdx.x;
    if (i < N_NODES) g_counts[i] = 0;
    if (i < 2 * NF) g_stats[i] = 0.0f;
}

// ---------------- CSR build ----------------
__global__ void count_kernel(const void* ei) {
    int is64 = g_is64;
    for (int e = blockIdx.x * blockDim.x + threadIdx.x; e < N_EDGES;
         e += gridDim.x * blockDim.x) {
        int d = load_index(ei, (long long)N_EDGES + e, is64);
        atomicAdd(&g_counts[d], 1);
    }
}

// hierarchical scan: per-block local exclusive scan + block sums
__global__ void scanA_kernel() {
    __shared__ int sm[256];
    int t = threadIdx.x;
    int i = blockIdx.x * 256 + t;
    int v = (i < N_NODES) ? g_counts[i] : 0;
    sm[t] = v;
    __syncthreads();
#pragma unroll
    for (int off = 1; off < 256; off <<= 1) {
        int tmp = (t >= off) ? sm[t - off] : 0;
        __syncthreads();
        sm[t] += tmp;
        __syncthreads();
    }
    if (i < N_NODES) g_offsets[i] = sm[t] - v;       // local exclusive
    if (t == 255) g_bsums[blockIdx.x] = sm[255];
}

__global__ void scanB_kernel() {
    __shared__ int sm[256];
    int t = threadIdx.x;
    int v = (t < SCAN_NBLK) ? g_bsums[t] : 0;
    sm[t] = v;
    __syncthreads();
#pragma unroll
    for (int off = 1; off < 256; off <<= 1) {
        int tmp = (t >= off) ? sm[t - off] : 0;
        __syncthreads();
        sm[t] += tmp;
        __syncthreads();
    }
    if (t < SCAN_NBLK) g_bpre[t] = sm[t] - v;
    if (t == 255) g_offsets[N_NODES] = sm[255];
}

__global__ void scanC_kernel() {
    int i = blockIdx.x * 256 + threadIdx.x;
    if (i < N_NODES) {
        int off = g_offsets[i] + g_bpre[i >> 8];
        g_offsets[i] = off;
        g_cursor[i] = off;
    }
}

__global__ void scatter_kernel(const void* ei) {
    int is64 = g_is64;
    for (int e = blockIdx.x * blockDim.x + threadIdx.x; e < N_EDGES;
         e += gridDim.x * blockDim.x) {
        int s = load_index(ei, e, is64);
        int d = load_index(ei, (long long)N_EDGES + e, is64);
        int pos = atomicAdd(&g_cursor[d], 1);
        g_srcidx[pos] = s;
    }
}

// ---------------- GIN aggregation: h = x + sum_{j->i} x_j ----------------
__global__ void agg_kernel(const float4* __restrict__ x4) {
    int node = blockIdx.x * 8 + (threadIdx.x >> 5);
    int lane = threadIdx.x & 31;
    if (node >= N_NODES) return;
    float4 acc = x4[node * 32 + lane];
    int e0 = g_offsets[node];
    int e1 = g_offsets[node + 1];
    for (int e = e0; e < e1; e++) {
        int s = g_srcidx[e];
        float4 v = x4[s * 32 + lane];
        acc.x += v.x; acc.y += v.y; acc.z += v.z; acc.w += v.w;
    }
    ((float4*)g_hin)[node * 32 + lane] = acc;
}

// ---------------- GEMM: out = relu(A[M,128] @ W[128,128] + b) ----------------
// Persistent grid: W loaded once per block; double-buffered A tiles.
// Optionally accumulates per-feature sum/sumsq of the relu output (BN stats).
#define AS_STRIDE 132
#define AS_ELEMS  (128 * AS_STRIDE)
#define GEMM_SMEM ((2 * AS_ELEMS + 128 * 128 + 128) * (int)sizeof(float))

__device__ __forceinline__ void load_A_tile(const float4* __restrict__ A4,
                                            float* As, int row0, int M, int t) {
    for (int i = t; i < 4096; i += 256) {
        int r = i >> 5;
        int c4 = i & 31;
        int gr = row0 + r;
        float4 v = (gr < M) ? A4[(long long)gr * 32 + c4]
                            : make_float4(0.f, 0.f, 0.f, 0.f);
        *(float4*)&As[r * AS_STRIDE + c4 * 4] = v;
    }
}

__global__ __launch_bounds__(256) void gemm_relu_kernel(
        const float* __restrict__ A, const float* __restrict__ W,
        const float* __restrict__ bias, float* __restrict__ out,
        int M, int do_stats) {
    extern __shared__ float smm[];
    float* As0 = smm;
    float* As1 = smm + AS_ELEMS;
    float* Ws  = smm + 2 * AS_ELEMS;
    float* bs  = Ws + 128 * 128;
    int t = threadIdx.x;
    int ntiles = (M + 127) >> 7;

    // load W + bias once
    const float4* W4 = (const float4*)W;
    float4* Ws4 = (float4*)Ws;
    for (int i = t; i < 4096; i += 256) Ws4[i] = W4[i];
    if (t < 128) bs[t] = bias[t];

    const float4* A4 = (const float4*)A;
    int tile = blockIdx.x;
    if (tile < ntiles) load_A_tile(A4, As0, tile * 128, M, t);
    __syncthreads();

    int tx = t & 15;   // 8 cols
    int ty = t >> 4;   // 8 rows
    float ls[8], lq[8];
#pragma unroll
    for (int j = 0; j < 8; j++) { ls[j] = 0.f; lq[j] = 0.f; }

    int buf = 0;
    for (; tile < ntiles; tile += gridDim.x) {
        float* Asc = buf ? As1 : As0;
        float* Asn = buf ? As0 : As1;
        int nt = tile + gridDim.x;
        if (nt < ntiles) load_A_tile(A4, Asn, nt * 128, M, t);

        float acc[8][8];
#pragma unroll
        for (int i = 0; i < 8; i++)
#pragma unroll
            for (int j = 0; j < 8; j++) acc[i][j] = 0.0f;

#pragma unroll 4
        for (int k = 0; k < 128; k++) {
            float a[8], w[8];
#pragma unroll
            for (int i = 0; i < 8; i++) a[i] = Asc[(ty * 8 + i) * AS_STRIDE + k];
            float4 w0 = *(const float4*)&Ws[k * 128 + tx * 8];
            float4 w1 = *(const float4*)&Ws[k * 128 + tx * 8 + 4];
            w[0] = w0.x; w[1] = w0.y; w[2] = w0.z; w[3] = w0.w;
            w[4] = w1.x; w[5] = w1.y; w[6] = w1.z; w[7] = w1.w;
#pragma unroll
            for (int i = 0; i < 8; i++)
#pragma unroll
                for (int j = 0; j < 8; j++) acc[i][j] += a[i] * w[j];
        }

        int row0 = tile * 128;
#pragma unroll
        for (int i = 0; i < 8; i++) {
            int gr = row0 + ty * 8 + i;
            if (gr < M) {
                float v[8];
#pragma unroll
                for (int j = 0; j < 8; j++) {
                    v[j] = fmaxf(acc[i][j] + bs[tx * 8 + j], 0.f);
                    ls[j] += v[j];
                    lq[j] += v[j] * v[j];
                }
                float4 o0 = make_float4(v[0], v[1], v[2], v[3]);
                float4 o1 = make_float4(v[4], v[5], v[6], v[7]);
                *(float4*)&out[(long long)gr * 128 + tx * 8] = o0;
                *(float4*)&out[(long long)gr * 128 + tx * 8 + 4] = o1;
            }
        }
        __syncthreads();
        buf ^= 1;
    }

    if (do_stats) {
        float* sstat = smm;  // reuse As0 region (all compute done, post-sync)
        if (t < 256) sstat[t] = 0.f;
        __syncthreads();
#pragma unroll
        for (int j = 0; j < 8; j++) {
            atomicAdd(&sstat[tx * 8 + j], ls[j]);
            atomicAdd(&sstat[128 + tx * 8 + j], lq[j]);
        }
        __syncthreads();
        if (t < 256) atomicAdd(&g_stats[t], sstat[t]);
    }
}

// ---------------- pooling + BN affine (BN folded after mean) ----------------
__global__ void pool_kernel(const void* batch, const float* __restrict__ gamma,
                            const float* __restrict__ beta) {
    int g = blockIdx.x;
    int f = threadIdx.x;
    int is64 = g_is64;
    __shared__ int se[2];
    if (f < 2) {
        int target = g + f;
        int lo = 0, hi = N_NODES;
        while (lo < hi) {
            int mid = (lo + hi) >> 1;
            int b = load_index(batch, mid, is64);
            if (b < target) lo = mid + 1; else hi = mid;
        }
        se[f] = lo;
    }
    __syncthreads();
    int s = se[0], e = se[1];
    float sum = 0.f;
    for (int r = s; r < e; r++) sum += g_x1[(long long)r * NF + f];
    float mu = g_stats[f] / (float)N_NODES;
    float var = g_stats[NF + f] / (float)N_NODES - mu * mu;
    float val = 0.f;
    if (e > s) {
        float m = sum / (float)(e - s);
        val = gamma[f] * (m - mu) * rsqrtf(var + BN_EPS) + beta[f];
    }
    g_xg[g * NF + f] = val;
}

// ---------------- fused recurrent gated loop (all 10 iterations) ----------
// Each graph row is independent. 64 blocks x 128 threads; 4 graphs/block.
// Weights transposed into smem once: Wt[c][k], row stride 260 (16B-aligned,
// conflict-free for float4 loads in 8-thread phases).
#define WT_STRIDE 260
#define RECUR_SMEM ((128 * WT_STRIDE + 128 + 4 * 256) * (int)sizeof(float))

__global__ __launch_bounds__(128) void recur_all_kernel(
        const float* __restrict__ Wl1, const float* __restrict__ bl1,
        const float* __restrict__ Wl2, const float* __restrict__ bl2) {
    extern __shared__ float sm[];
    float* Wt  = sm;                       // [128][260]
    float* bs  = Wt + 128 * WT_STRIDE;     // [128]
    float* cat = bs + 128;                 // [4][256]
    int t = threadIdx.x;                   // output column
    int g0 = blockIdx.x * 4;

    // transpose-load weights: col c<64 -> Wl2 (tanh half), c>=64 -> Wl1
    for (int idx = t; idx < 256 * 64; idx += 128) {
        int k = idx >> 6, c = idx & 63;
        float w2 = Wl2[idx];
        float w1 = Wl1[idx];
        Wt[c * WT_STRIDE + k] = w2;
        Wt[(c + 64) * WT_STRIDE + k] = w1;
    }
    bs[t] = (t < 64) ? bl2[t] : bl1[t - 64];
#pragma unroll
    for (int r = 0; r < 4; r++) {
        float xv = g_xg[(g0 + r) * NF + t];
        cat[r * 256 + t] = xv;          // xg half (constant)
        cat[r * 256 + 128 + t] = xv;    // h init = xg
    }
    __syncthreads();

    const float* w = &Wt[t * WT_STRIDE];
    float bias = bs[t];
    for (int it = 0; it < N_ITERS; it++) {
        float a0 = bias, a1 = bias, a2 = bias, a3 = bias;
#pragma unroll 8
        for (int k = 0; k < 256; k += 4) {
            float4 wv = *(const float4*)&w[k];
            float4 c0 = *(const float4*)&cat[0 * 256 + k];
            float4 c1 = *(const float4*)&cat[1 * 256 + k];
            float4 c2 = *(const float4*)&cat[2 * 256 + k];
            float4 c3 = *(const float4*)&cat[3 * 256 + k];
            a0 += c0.x * wv.x + c0.y * wv.y + c0.z * wv.z + c0.w * wv.w;
            a1 += c1.x * wv.x + c1.y * wv.y + c1.z * wv.z + c1.w * wv.w;
            a2 += c2.x * wv.x + c2.y * wv.y + c2.z * wv.z + c2.w * wv.w;
            a3 += c3.x * wv.x + c3.y * wv.y + c3.z * wv.z + c3.w * wv.w;
        }
        float o[4] = {a0, a1, a2, a3};
        float v[4];
#pragma unroll
        for (int r = 0; r < 4; r++)
            v[r] = (t < 64) ? tanhf(o[r]) : (1.0f / (1.0f + expf(-o[r])));
        __syncthreads();
#pragma unroll
        for (int r = 0; r < 4; r++) cat[r * 256 + 128 + t] = v[r];
        __syncthreads();
    }
#pragma unroll
    for (int r = 0; r < 4; r++)
        g_h0[(g0 + r) * NF + t] = cat[r * 256 + 128 + t];
}

// ---------------- output MLP ----------------
__global__ void mlp_kernel(const float* __restrict__ Wm1, const float* __restrict__ bm1,
                           const float* __restrict__ Wm2, const float* __restrict__ bm2,
                           float* __restrict__ out) {
    int g = blockIdx.x;
    int t = threadIdx.x;   // 128
    __shared__ float hrow[NF];
    __shared__ float hid[DIM];
    hrow[t] = g_h0[g * NF + t];
    __syncthreads();
    if (t < DIM) {
        float a = bm1[t];
#pragma unroll 8
        for (int k = 0; k < NF; k++) a += hrow[k] * Wm1[k * DIM + t];
        hid[t] = fmaxf(a, 0.f);
    }
    __syncthreads();
    if (t < N_OUT) {
        float a = bm2[t];
        for (int k = 0; k < DIM; k++) a += hid[k] * Wm2[k * N_OUT + t];
        out[g * N_OUT + t] = a;
    }
}

// ---------------- host ----------------
extern "C" void kernel_launch(void* const* d_in, const int* in_sizes, int n_in,
                              void* d_out, int out_size) {
    const float* x     = (const float*)d_in[0];
    const void*  ei    = d_in[1];
    const void*  batch = d_in[2];
    const float* W1a = (const float*)d_in[3];
    const float* b1a = (const float*)d_in[4];
    const float* W1b = (const float*)d_in[5];
    const float* b1b = (const float*)d_in[6];
    const float* gamma = (const float*)d_in[7];
    const float* beta  = (const float*)d_in[8];
    const float* Wl1 = (const float*)d_in[9];
    const float* bl1 = (const float*)d_in[10];
    const float* Wl2 = (const float*)d_in[11];
    const float* bl2 = (const float*)d_in[12];
    const float* Wm1 = (const float*)d_in[13];
    const float* bm1 = (const float*)d_in[14];
    const float* Wm2 = (const float*)d_in[15];
    const float* bm2 = (const float*)d_in[16];
    float* out = (float*)d_out;

    void *p_hin, *p_t1, *p_x1;
    cudaGetSymbolAddress(&p_hin, g_hin);
    cudaGetSymbolAddress(&p_t1, g_t1);
    cudaGetSymbolAddress(&p_x1, g_x1);

    cudaFuncSetAttribute(gemm_relu_kernel,
                         cudaFuncAttributeMaxDynamicSharedMemorySize, GEMM_SMEM);
    cudaFuncSetAttribute(recur_all_kernel,
                         cudaFuncAttributeMaxDynamicSharedMemorySize, RECUR_SMEM);

    detect_kernel<<<1, 32>>>((const int*)ei);
    init_kernel<<<(N_NODES + 255) / 256, 256>>>();
    count_kernel<<<1024, 256>>>(ei);
    scanA_kernel<<<SCAN_NBLK, 256>>>();
    scanB_kernel<<<1, 256>>>();
    scanC_kernel<<<SCAN_NBLK, 256>>>();
    scatter_kernel<<<1024, 256>>>(ei);
    agg_kernel<<<(N_NODES + 7) / 8, 256>>>((const float4*)x);
    gemm_relu_kernel<<<148, 256, GEMM_SMEM>>>(
        (const float*)p_hin, W1a, b1a, (float*)p_t1, N_NODES, 0);
    gemm_relu_kernel<<<148, 256, GEMM_SMEM>>>(
        (const float*)p_t1, W1b, b1b, (float*)p_x1, N_NODES, 1);
    pool_kernel<<<N_GRAPHS, 128>>>(batch, gamma, beta);
    recur_all_kernel<<<N_GRAPHS / 4, 128, RECUR_SMEM>>>(Wl1, bl1, Wl2, bl2);
    mlp_kernel<<<N_GRAPHS, 128>>>(Wm1, bm1, Wm2, bm2, out);
}

// round 4
// speedup vs baseline: 2.2015x; 1.2617x over previous
#include <cuda_runtime.h>
#include <cuda_bf16.h>
#include <math.h>
#include <stdint.h>

#define N_NODES  50000
#define N_EDGES  600000
#define NF       128
#define N_GRAPHS 256
#define DIM      95
#define N_OUT    12
#define N_ITERS  10
#define BN_EPS   1e-5f
#define SCAN_NBLK 196
#define NTILES   391             // ceil(50000/128)

// ---------------- scratch ----------------
__device__ unsigned g_ahi[N_NODES * 64];   // bf16x2 packed: (x+agg) hi
__device__ unsigned g_alo[N_NODES * 64];   // lo
__device__ unsigned g_t1hi[N_NODES * 64];  // relu(h@W1a+b1a) hi
__device__ unsigned g_t1lo[N_NODES * 64];
__device__ float g_x1[N_NODES * NF];
__device__ int   g_counts[N_NODES];
__device__ int   g_offsets[N_NODES + 1];
__device__ int   g_cursor[N_NODES];
__device__ int   g_srcidx[N_EDGES];
__device__ int   g_bsums[SCAN_NBLK];
__device__ int   g_bpre[SCAN_NBLK];
__device__ float g_stats[2 * NF];
__device__ float g_xg[N_GRAPHS * NF];
__device__ float g_h0[N_GRAPHS * NF];
__device__ int   g_is64;

// ---------------- helpers ----------------
__device__ __forceinline__ uint32_t smem_u32(const void* p) {
    uint32_t a;
    asm("{ .reg .u64 t; cvta.to.shared.u64 t, %1; cvt.u32.u64 %0, t; }" : "=r"(a) : "l"(p));
    return a;
}
__device__ __forceinline__ void split_bf(float v, unsigned short& h, unsigned short& l) {
    __nv_bfloat16 hb = __float2bfloat16(v);
    float r = v - __bfloat162float(hb);
    __nv_bfloat16 lb = __float2bfloat16(r);
    h = __bfloat16_as_ushort(hb);
    l = __bfloat16_as_ushort(lb);
}
__device__ __forceinline__ void ldsm_x4(uint32_t* r, uint32_t addr) {
    asm volatile("ldmatrix.sync.aligned.m8n8.x4.shared.b16 {%0,%1,%2,%3}, [%4];"
        : "=r"(r[0]), "=r"(r[1]), "=r"(r[2]), "=r"(r[3]) : "r"(addr));
}
__device__ __forceinline__ void ldsm_x4_t(uint32_t* r, uint32_t addr) {
    asm volatile("ldmatrix.sync.aligned.m8n8.x4.trans.shared.b16 {%0,%1,%2,%3}, [%4];"
        : "=r"(r[0]), "=r"(r[1]), "=r"(r[2]), "=r"(r[3]) : "r"(addr));
}
__device__ __forceinline__ void mma_bf16(float* c, const uint32_t* a,
                                         uint32_t b0, uint32_t b1) {
    asm volatile("mma.sync.aligned.m16n8k16.row.col.f32.bf16.bf16.f32 "
        "{%0,%1,%2,%3}, {%4,%5,%6,%7}, {%8,%9}, {%0,%1,%2,%3};"
        : "+f"(c[0]), "+f"(c[1]), "+f"(c[2]), "+f"(c[3])
        : "r"(a[0]), "r"(a[1]), "r"(a[2]), "r"(a[3]), "r"(b0), "r"(b1));
}

// ---------------- dtype probe ----------------
__global__ void detect_kernel(const int* ei32) {
    int bad = 0;
    for (int i = threadIdx.x; i < 1024; i += 32)
        if (ei32[2 * i + 1] != 0) bad = 1;
    unsigned m = __ballot_sync(0xffffffffu, bad);
    if (threadIdx.x == 0) g_is64 = (m == 0) ? 1 : 0;
}
__device__ __forceinline__ int load_index(const void* p, long long i, int is64) {
    if (is64) return (int)((const long long*)p)[i];
    return ((const int*)p)[i];
}

// ---------------- init ----------------
__global__ void init_kernel() {
    int i = blockIdx.x * blockDim.x + threadIdx.x;
    if (i < N_NODES) g_counts[i] = 0;
    if (i < 2 * NF) g_stats[i] = 0.0f;
}

// ---------------- CSR build ----------------
__global__ void count_kernel(const void* ei) {
    int is64 = g_is64;
    for (int e = blockIdx.x * blockDim.x + threadIdx.x; e < N_EDGES;
         e += gridDim.x * blockDim.x) {
        int d = load_index(ei, (long long)N_EDGES + e, is64);
        atomicAdd(&g_counts[d], 1);
    }
}
__global__ void scanA_kernel() {
    __shared__ int sm[256];
    int t = threadIdx.x;
    int i = blockIdx.x * 256 + t;
    int v = (i < N_NODES) ? g_counts[i] : 0;
    sm[t] = v;
    __syncthreads();
#pragma unroll
    for (int off = 1; off < 256; off <<= 1) {
        int tmp = (t >= off) ? sm[t - off] : 0;
        __syncthreads();
        sm[t] += tmp;
        __syncthreads();
    }
    if (i < N_NODES) g_offsets[i] = sm[t] - v;
    if (t == 255) g_bsums[blockIdx.x] = sm[255];
}
__global__ void scanB_kernel() {
    __shared__ int sm[256];
    int t = threadIdx.x;
    int v = (t < SCAN_NBLK) ? g_bsums[t] : 0;
    sm[t] = v;
    __syncthreads();
#pragma unroll
    for (int off = 1; off < 256; off <<= 1) {
        int tmp = (t >= off) ? sm[t - off] : 0;
        __syncthreads();
        sm[t] += tmp;
        __syncthreads();
    }
    if (t < SCAN_NBLK) g_bpre[t] = sm[t] - v;
    if (t == 255) g_offsets[N_NODES] = sm[255];
}
__global__ void scanC_kernel() {
    int i = blockIdx.x * 256 + threadIdx.x;
    if (i < N_NODES) {
        int off = g_offsets[i] + g_bpre[i >> 8];
        g_offsets[i] = off;
        g_cursor[i] = off;
    }
}
__global__ void scatter_kernel(const void* ei) {
    int is64 = g_is64;
    for (int e = blockIdx.x * blockDim.x + threadIdx.x; e < N_EDGES;
         e += gridDim.x * blockDim.x) {
        int s = load_index(ei, e, is64);
        int d = load_index(ei, (long long)N_EDGES + e, is64);
        int pos = atomicAdd(&g_cursor[d], 1);
        g_srcidx[pos] = s;
    }
}

// ---------------- GIN aggregation -> bf16 hi/lo ----------------
__global__ void agg_kernel(const float4* __restrict__ x4) {
    int node = blockIdx.x * 8 + (threadIdx.x >> 5);
    int lane = threadIdx.x & 31;
    if (node >= N_NODES) return;
    float4 acc = x4[node * 32 + lane];
    int e0 = g_offsets[node];
    int e1 = g_offsets[node + 1];
    for (int e = e0; e < e1; e++) {
        int s = g_srcidx[e];
        float4 v = x4[s * 32 + lane];
        acc.x += v.x; acc.y += v.y; acc.z += v.z; acc.w += v.w;
    }
    float vv[4] = {acc.x, acc.y, acc.z, acc.w};
    unsigned short h[4], l[4];
#pragma unroll
    for (int i = 0; i < 4; i++) split_bf(vv[i], h[i], l[i]);
    uint2 hv = make_uint2((unsigned)h[0] | ((unsigned)h[1] << 16),
                          (unsigned)h[2] | ((unsigned)h[3] << 16));
    uint2 lv = make_uint2((unsigned)l[0] | ((unsigned)l[1] << 16),
                          (unsigned)l[2] | ((unsigned)l[3] << 16));
    ((uint2*)g_ahi)[node * 32 + lane] = hv;
    ((uint2*)g_alo)[node * 32 + lane] = lv;
}

// ---------------- tensor-core GEMM (mma.sync bf16 hi/lo split) -------------
// out = relu(A[M,128] @ W[128,128] + b), A given as bf16 hi/lo.
// mode 0: write bf16 hi/lo packed; mode 1: write fp32 + BN stats.
// smem: A tiles [128][136] bf16 (hi/lo), W [128][136] bf16 (hi/lo), bias.
// sV (fp32 [128][132]) reuses the A-tile region after compute.
#define SA_HI 0
#define SA_LO 34816
#define SW_HI 69632
#define SW_LO 104448
#define SBIAS 139264
#define GEMM_SMEM 139776

__global__ __launch_bounds__(256, 1) void gemm_mma_kernel(
        const unsigned* __restrict__ Ahi, const unsigned* __restrict__ Alo,
        const float* __restrict__ W, const float* __restrict__ bias,
        unsigned* __restrict__ out_hi, unsigned* __restrict__ out_lo,
        float* __restrict__ out_f32, int M, int mode) {
    extern __shared__ char smem[];
    uint32_t sbase = smem_u32(smem);
    float* sV = (float*)smem;                   // overlaps A region (post-compute)
    float* sBias = (float*)(smem + SBIAS);
    unsigned* aHiW = (unsigned*)(smem + SA_HI); // rows of 68 uints (136 bf16)
    unsigned* aLoW = (unsigned*)(smem + SA_LO);
    int t = threadIdx.x;
    int lane = t & 31;
    int w = t >> 5;
    int m0 = w * 16;

    // split W -> smem hi/lo, once (W[k][n] row-major == B[k][n] for row.col mma)
    for (int idx = t; idx < 128 * 128; idx += 256) {
        int k = idx >> 7, n = idx & 127;
        unsigned short h, l;
        split_bf(W[idx], h, l);
        *(unsigned short*)(smem + SW_HI + (k * 136 + n) * 2) = h;
        *(unsigned short*)(smem + SW_LO + (k * 136 + n) * 2) = l;
    }
    if (t < 128) sBias[t] = bias[t];

    // ldmatrix lane address components (same formula for A and B-trans)
    int lrow = (lane & 7) + ((lane >> 3) & 1) * 8;
    int lcol = (lane >> 4) * 8;
    uint32_t aBaseHi = sbase + SA_HI + ((m0 + lrow) * 136 + lcol) * 2;
    uint32_t aBaseLo = aBaseHi + (SA_LO - SA_HI);
    uint32_t bBaseHi = sbase + SW_HI + (lrow * 136 + lcol) * 2;
    uint32_t bBaseLo = bBaseHi + (SW_LO - SW_HI);

    for (int tile = blockIdx.x; tile < NTILES; tile += gridDim.x) {
        int row0 = tile << 7;
        // load A tile hi/lo (each row: 64 uints = 128 bf16)
        for (int idx = t; idx < 8192; idx += 256) {
            int r = idx >> 6, c2 = idx & 63;
            int gr = row0 + r;
            unsigned vh = 0, vl = 0;
            if (gr < M) { vh = Ahi[gr * 64 + c2]; vl = Alo[gr * 64 + c2]; }
            aHiW[r * 68 + c2] = vh;
            aLoW[r * 68 + c2] = vl;
        }
        __syncthreads();

        float c[16][4];
#pragma unroll
        for (int j = 0; j < 16; j++)
#pragma unroll
            for (int q = 0; q < 4; q++) c[j][q] = 0.f;

#pragma unroll 1
        for (int ks = 0; ks < 8; ks++) {
            uint32_t ah[4], al[4];
            ldsm_x4(ah, aBaseHi + ks * 32);
            ldsm_x4(al, aBaseLo + ks * 32);
#pragma unroll
            for (int nj = 0; nj < 8; nj++) {
                uint32_t bh[4], bl[4];
                uint32_t bo = (uint32_t)ks * (16 * 136 * 2) + nj * 32;
                ldsm_x4_t(bh, bBaseHi + bo);
                ldsm_x4_t(bl, bBaseLo + bo);
                mma_bf16(c[2 * nj],     ah, bh[0], bh[1]);
                mma_bf16(c[2 * nj + 1], ah, bh[2], bh[3]);
                mma_bf16(c[2 * nj],     ah, bl[0], bl[1]);
                mma_bf16(c[2 * nj + 1], ah, bl[2], bl[3]);
                mma_bf16(c[2 * nj],     al, bh[0], bh[1]);
                mma_bf16(c[2 * nj + 1], al, bh[2], bh[3]);
            }
        }
        __syncthreads();   // everyone done reading A smem -> safe to write sV

        // epilogue: bias + relu -> sV
        int er = m0 + (lane >> 2);
        int ec = 2 * (lane & 3);
#pragma unroll
        for (int j = 0; j < 16; j++) {
            int n = j * 8 + ec;
            float b0 = sBias[n], b1 = sBias[n + 1];
            float2 v01 = make_float2(fmaxf(c[j][0] + b0, 0.f), fmaxf(c[j][1] + b1, 0.f));
            float2 v23 = make_float2(fmaxf(c[j][2] + b0, 0.f), fmaxf(c[j][3] + b1, 0.f));
            *(float2*)&sV[er * 132 + n] = v01;
            *(float2*)&sV[(er + 8) * 132 + n] = v23;
        }
        __syncthreads();

        if (mode == 0) {
            for (int idx = t; idx < 128 * 64; idx += 256) {
                int r = idx >> 6, c2 = idx & 63;
                int gr = row0 + r;
                if (gr < M) {
                    float v0 = sV[r * 132 + c2 * 2];
                    float v1 = sV[r * 132 + c2 * 2 + 1];
                    unsigned short h0, l0, h1, l1;
                    split_bf(v0, h0, l0);
                    split_bf(v1, h1, l1);
                    out_hi[gr * 64 + c2] = (unsigned)h0 | ((unsigned)h1 << 16);
                    out_lo[gr * 64 + c2] = (unsigned)l0 | ((unsigned)l1 << 16);
                }
            }
        } else {
            for (int idx = t; idx < 128 * 32; idx += 256) {
                int r = idx >> 5, c4 = (idx & 31) * 4;
                int gr = row0 + r;
                if (gr < M) {
                    float4 v = make_float4(sV[r * 132 + c4], sV[r * 132 + c4 + 1],
                                           sV[r * 132 + c4 + 2], sV[r * 132 + c4 + 3]);
                    *(float4*)&out_f32[(long long)gr * 128 + c4] = v;
                }
            }
            if (t < 128) {
                float s = 0.f, q = 0.f;
                int rmax = M - row0;
                if (rmax > 128) rmax = 128;
                for (int r = 0; r < rmax; r++) {
                    float v = sV[r * 132 + t];
                    s += v;
                    q += v * v;
                }
                atomicAdd(&g_stats[t], s);
                atomicAdd(&g_stats[128 + t], q);
            }
        }
        __syncthreads();   // before next tile's A load overwrites sV
    }
}

// ---------------- pooling + BN affine ----------------
__global__ void pool_kernel(const void* batch, const float* __restrict__ gamma,
                            const float* __restrict__ beta) {
    int g = blockIdx.x;
    int f = threadIdx.x;
    int is64 = g_is64;
    __shared__ int se[2];
    if (f < 2) {
        int target = g + f;
        int lo = 0, hi = N_NODES;
        while (lo < hi) {
            int mid = (lo + hi) >> 1;
            int b = load_index(batch, mid, is64);
            if (b < target) lo = mid + 1; else hi = mid;
        }
        se[f] = lo;
    }
    __syncthreads();
    int s = se[0], e = se[1];
    float sum = 0.f;
    for (int r = s; r < e; r++) sum += g_x1[(long long)r * NF + f];
    float mu = g_stats[f] / (float)N_NODES;
    float var = g_stats[NF + f] / (float)N_NODES - mu * mu;
    float val = 0.f;
    if (e > s) {
        float m = sum / (float)(e - s);
        val = gamma[f] * (m - mu) * rsqrtf(var + BN_EPS) + beta[f];
    }
    g_xg[g * NF + f] = val;
}

// ---------------- fused recurrent loop ----------------
#define WT_STRIDE 260
#define RECUR_SMEM ((128 * WT_STRIDE + 128 + 4 * 256) * (int)sizeof(float))

__global__ __launch_bounds__(128) void recur_all_kernel(
        const float* __restrict__ Wl1, const float* __restrict__ bl1,
        const float* __restrict__ Wl2, const float* __restrict__ bl2) {
    extern __shared__ float sm[];
    float* Wt  = sm;
    float* bs  = Wt + 128 * WT_STRIDE;
    float* cat = bs + 128;
    int t = threadIdx.x;
    int g0 = blockIdx.x * 4;

    for (int idx = t; idx < 256 * 64; idx += 128) {
        int k = idx >> 6, c = idx & 63;
        Wt[c * WT_STRIDE + k] = Wl2[idx];
        Wt[(c + 64) * WT_STRIDE + k] = Wl1[idx];
    }
    bs[t] = (t < 64) ? bl2[t] : bl1[t - 64];
#pragma unroll
    for (int r = 0; r < 4; r++) {
        float xv = g_xg[(g0 + r) * NF + t];
        cat[r * 256 + t] = xv;
        cat[r * 256 + 128 + t] = xv;
    }
    __syncthreads();

    const float* w = &Wt[t * WT_STRIDE];
    float bias = bs[t];
    for (int it = 0; it < N_ITERS; it++) {
        float a0 = bias, a1 = bias, a2 = bias, a3 = bias;
#pragma unroll 8
        for (int k = 0; k < 256; k += 4) {
            float4 wv = *(const float4*)&w[k];
            float4 c0 = *(const float4*)&cat[0 * 256 + k];
            float4 c1 = *(const float4*)&cat[1 * 256 + k];
            float4 c2 = *(const float4*)&cat[2 * 256 + k];
            float4 c3 = *(const float4*)&cat[3 * 256 + k];
            a0 += c0.x * wv.x + c0.y * wv.y + c0.z * wv.z + c0.w * wv.w;
            a1 += c1.x * wv.x + c1.y * wv.y + c1.z * wv.z + c1.w * wv.w;
            a2 += c2.x * wv.x + c2.y * wv.y + c2.z * wv.z + c2.w * wv.w;
            a3 += c3.x * wv.x + c3.y * wv.y + c3.z * wv.z + c3.w * wv.w;
        }
        float o[4] = {a0, a1, a2, a3};
        float v[4];
#pragma unroll
        for (int r = 0; r < 4; r++)
            v[r] = (t < 64) ? tanhf(o[r]) : (1.0f / (1.0f + expf(-o[r])));
        __syncthreads();
#pragma unroll
        for (int r = 0; r < 4; r++) cat[r * 256 + 128 + t] = v[r];
        __syncthreads();
    }
#pragma unroll
    for (int r = 0; r < 4; r++)
        g_h0[(g0 + r) * NF + t] = cat[r * 256 + 128 + t];
}

// ---------------- output MLP ----------------
__global__ void mlp_kernel(const float* __restrict__ Wm1, const float* __restrict__ bm1,
                           const float* __restrict__ Wm2, const float* __restrict__ bm2,
                           float* __restrict__ out) {
    int g = blockIdx.x;
    int t = threadIdx.x;
    __shared__ float hrow[NF];
    __shared__ float hid[DIM];
    hrow[t] = g_h0[g * NF + t];
    __syncthreads();
    if (t < DIM) {
        float a = bm1[t];
#pragma unroll 8
        for (int k = 0; k < NF; k++) a += hrow[k] * Wm1[k * DIM + t];
        hid[t] = fmaxf(a, 0.f);
    }
    __syncthreads();
    if (t < N_OUT) {
        float a = bm2[t];
        for (int k = 0; k < DIM; k++) a += hid[k] * Wm2[k * N_OUT + t];
        out[g * N_OUT + t] = a;
    }
}

// ---------------- host ----------------
extern "C" void kernel_launch(void* const* d_in, const int* in_sizes, int n_in,
                              void* d_out, int out_size) {
    const float* x     = (const float*)d_in[0];
    const void*  ei    = d_in[1];
    const void*  batch = d_in[2];
    const float* W1a = (const float*)d_in[3];
    const float* b1a = (const float*)d_in[4];
    const float* W1b = (const float*)d_in[5];
    const float* b1b = (const float*)d_in[6];
    const float* gamma = (const float*)d_in[7];
    const float* beta  = (const float*)d_in[8];
    const float* Wl1 = (const float*)d_in[9];
    const float* bl1 = (const float*)d_in[10];
    const float* Wl2 = (const float*)d_in[11];
    const float* bl2 = (const float*)d_in[12];
    const float* Wm1 = (const float*)d_in[13];
    const float* bm1 = (const float*)d_in[14];
    const float* Wm2 = (const float*)d_in[15];
    const float* bm2 = (const float*)d_in[16];
    float* out = (float*)d_out;

    void *p_ahi, *p_alo, *p_t1hi, *p_t1lo, *p_x1;
    cudaGetSymbolAddress(&p_ahi, g_ahi);
    cudaGetSymbolAddress(&p_alo, g_alo);
    cudaGetSymbolAddress(&p_t1hi, g_t1hi);
    cudaGetSymbolAddress(&p_t1lo, g_t1lo);
    cudaGetSymbolAddress(&p_x1, g_x1);

    cudaFuncSetAttribute(gemm_mma_kernel,
                         cudaFuncAttributeMaxDynamicSharedMemorySize, GEMM_SMEM);
    cudaFuncSetAttribute(recur_all_kernel,
                         cudaFuncAttributeMaxDynamicSharedMemorySize, RECUR_SMEM);

    detect_kernel<<<1, 32>>>((const int*)ei);
    init_kernel<<<(N_NODES + 255) / 256, 256>>>();
    count_kernel<<<1024, 256>>>(ei);
    scanA_kernel<<<SCAN_NBLK, 256>>>();
    scanB_kernel<<<1, 256>>>();
    scanC_kernel<<<SCAN_NBLK, 256>>>();
    scatter_kernel<<<1024, 256>>>(ei);
    agg_kernel<<<(N_NODES + 7) / 8, 256>>>((const float4*)x);
    gemm_mma_kernel<<<148, 256, GEMM_SMEM>>>(
        (const unsigned*)p_ahi, (const unsigned*)p_alo, W1a, b1a,
        (unsigned*)p_t1hi, (unsigned*)p_t1lo, nullptr, N_NODES, 0);
    gemm_mma_kernel<<<148, 256, GEMM_SMEM>>>(
        (const unsigned*)p_t1hi, (const unsigned*)p_t1lo, W1b, b1b,
        nullptr, nullptr, (float*)p_x1, N_NODES, 1);
    pool_kernel<<<N_GRAPHS, 128>>>(batch, gamma, beta);
    recur_all_kernel<<<N_GRAPHS / 4, 128, RECUR_SMEM>>>(Wl1, bl1, Wl2, bl2);
    mlp_kernel<<<N_GRAPHS, 128>>>(Wm1, bm1, Wm2, bm2, out);
}

// round 5
// speedup vs baseline: 2.3146x; 1.0514x over previous
#include <cuda_runtime.h>
#include <cuda_bf16.h>
#include <math.h>
#include <stdint.h>

#define N_NODES  50000
#define N_EDGES  600000
#define NF       128
#define N_GRAPHS 256
#define DIM      95
#define N_OUT    12
#define N_ITERS  10
#define BN_EPS   1e-5f
#define SCAN_NBLK 196
#define NTILES   391             // ceil(50000/128)

// ---------------- scratch ----------------
__device__ unsigned g_ahi[N_NODES * 64];   // bf16x2 packed: (x+agg) hi
__device__ unsigned g_alo[N_NODES * 64];
__device__ unsigned g_t1hi[N_NODES * 64];
__device__ unsigned g_t1lo[N_NODES * 64];
__device__ int   g_counts[N_NODES];
__device__ int   g_offsets[N_NODES + 1];
__device__ int   g_cursor[N_NODES];
__device__ int   g_srcidx[N_EDGES];
__device__ int   g_bsums[SCAN_NBLK];
__device__ int   g_bpre[SCAN_NBLK];
__device__ float g_stats[2 * NF];          // BN sum / sumsq
__device__ float g_gsum[N_GRAPHS * NF];    // per-graph sums of x1 (pre-affine)
__device__ int   g_is64;

// ---------------- helpers ----------------
__device__ __forceinline__ uint32_t smem_u32(const void* p) {
    uint32_t a;
    asm("{ .reg .u64 t; cvta.to.shared.u64 t, %1; cvt.u32.u64 %0, t; }" : "=r"(a) : "l"(p));
    return a;
}
__device__ __forceinline__ void split_bf(float v, unsigned short& h, unsigned short& l) {
    __nv_bfloat16 hb = __float2bfloat16(v);
    float r = v - __bfloat162float(hb);
    __nv_bfloat16 lb = __float2bfloat16(r);
    h = __bfloat16_as_ushort(hb);
    l = __bfloat16_as_ushort(lb);
}
__device__ __forceinline__ void ldsm_x4(uint32_t* r, uint32_t addr) {
    asm volatile("ldmatrix.sync.aligned.m8n8.x4.shared.b16 {%0,%1,%2,%3}, [%4];"
        : "=r"(r[0]), "=r"(r[1]), "=r"(r[2]), "=r"(r[3]) : "r"(addr));
}
__device__ __forceinline__ void ldsm_x4_t(uint32_t* r, uint32_t addr) {
    asm volatile("ldmatrix.sync.aligned.m8n8.x4.trans.shared.b16 {%0,%1,%2,%3}, [%4];"
        : "=r"(r[0]), "=r"(r[1]), "=r"(r[2]), "=r"(r[3]) : "r"(addr));
}
__device__ __forceinline__ void mma_bf16(float* c, const uint32_t* a,
                                         uint32_t b0, uint32_t b1) {
    asm volatile("mma.sync.aligned.m16n8k16.row.col.f32.bf16.bf16.f32 "
        "{%0,%1,%2,%3}, {%4,%5,%6,%7}, {%8,%9}, {%0,%1,%2,%3};"
        : "+f"(c[0]), "+f"(c[1]), "+f"(c[2]), "+f"(c[3])
        : "r"(a[0]), "r"(a[1]), "r"(a[2]), "r"(a[3]), "r"(b0), "r"(b1));
}
__device__ __forceinline__ int load_index(const void* p, long long i, int is64) {
    if (is64) return (int)((const long long*)p)[i];
    return ((const int*)p)[i];
}

// ---------------- init (+ dtype probe in block 0) ----------------
__global__ void init_kernel(const int* ei32) {
    int i = blockIdx.x * blockDim.x + threadIdx.x;
    if (i < N_NODES) g_counts[i] = 0;
    if (i < 2 * NF) g_stats[i] = 0.0f;
    if (i < N_GRAPHS * NF) g_gsum[i] = 0.0f;
    if (blockIdx.x == 0 && threadIdx.x < 32) {
        int bad = 0;
        for (int j = threadIdx.x; j < 1024; j += 32)
            if (ei32[2 * j + 1] != 0) bad = 1;
        unsigned m = __ballot_sync(0xffffffffu, bad);
        if (threadIdx.x == 0) g_is64 = (m == 0) ? 1 : 0;
    }
}

// ---------------- CSR build ----------------
__global__ void count_kernel(const void* ei) {
    int is64 = g_is64;
    for (int e = blockIdx.x * blockDim.x + threadIdx.x; e < N_EDGES;
         e += gridDim.x * blockDim.x) {
        int d = load_index(ei, (long long)N_EDGES + e, is64);
        atomicAdd(&g_counts[d], 1);
    }
}

__global__ void scanA_kernel() {
    __shared__ int ws[8];
    int t = threadIdx.x, lane = t & 31, w = t >> 5;
    int i = blockIdx.x * 256 + t;
    int v = (i < N_NODES) ? g_counts[i] : 0;
    int x = v;
#pragma unroll
    for (int o = 1; o < 32; o <<= 1) {
        int y = __shfl_up_sync(0xffffffffu, x, o);
        if (lane >= o) x += y;
    }
    if (lane == 31) ws[w] = x;
    __syncthreads();
    if (w == 0) {
        int y = (lane < 8) ? ws[lane] : 0;
#pragma unroll
        for (int o = 1; o < 32; o <<= 1) {
            int z = __shfl_up_sync(0xffffffffu, y, o);
            if (lane >= o) y += z;
        }
        if (lane < 8) ws[lane] = y;   // inclusive warp totals
    }
    __syncthreads();
    int pre = ((w > 0) ? ws[w - 1] : 0) + x - v;
    if (i < N_NODES) g_offsets[i] = pre;
    if (t == 255) g_bsums[blockIdx.x] = ws[7];
}

__global__ void scanB_kernel() {
    __shared__ int ws[8];
    int t = threadIdx.x, lane = t & 31, w = t >> 5;
    int v = (t < SCAN_NBLK) ? g_bsums[t] : 0;
    int x = v;
#pragma unroll
    for (int o = 1; o < 32; o <<= 1) {
        int y = __shfl_up_sync(0xffffffffu, x, o);
        if (lane >= o) x += y;
    }
    if (lane == 31) ws[w] = x;
    __syncthreads();
    if (w == 0) {
        int y = (lane < 8) ? ws[lane] : 0;
#pragma unroll
        for (int o = 1; o < 32; o <<= 1) {
            int z = __shfl_up_sync(0xffffffffu, y, o);
            if (lane >= o) y += z;
        }
        if (lane < 8) ws[lane] = y;
    }
    __syncthreads();
    int pre = ((w > 0) ? ws[w - 1] : 0) + x - v;
    if (t < SCAN_NBLK) g_bpre[t] = pre;
    if (t == 255) g_offsets[N_NODES] = ws[7];
}

__global__ void scanC_kernel() {
    int i = blockIdx.x * 256 + threadIdx.x;
    if (i < N_NODES) {
        int off = g_offsets[i] + g_bpre[i >> 8];
        g_offsets[i] = off;
        g_cursor[i] = off;
    }
}

__global__ void scatter_kernel(const void* ei) {
    int is64 = g_is64;
    for (int e = blockIdx.x * blockDim.x + threadIdx.x; e < N_EDGES;
         e += gridDim.x * blockDim.x) {
        int s = load_index(ei, e, is64);
        int d = load_index(ei, (long long)N_EDGES + e, is64);
        int pos = atomicAdd(&g_cursor[d], 1);
        g_srcidx[pos] = s;
    }
}

// ---------------- GIN aggregation -> bf16 hi/lo (4x unrolled gather) -------
__global__ void agg_kernel(const float4* __restrict__ x4) {
    int node = blockIdx.x * 8 + (threadIdx.x >> 5);
    int lane = threadIdx.x & 31;
    if (node >= N_NODES) return;
    float4 acc = x4[node * 32 + lane];
    int e0 = g_offsets[node];
    int e1 = g_offsets[node + 1];
    int e = e0;
    int n4 = e0 + ((e1 - e0) & ~3);
    for (; e < n4; e += 4) {
        int s0 = g_srcidx[e], s1 = g_srcidx[e + 1];
        int s2 = g_srcidx[e + 2], s3 = g_srcidx[e + 3];
        float4 v0 = x4[s0 * 32 + lane];
        float4 v1 = x4[s1 * 32 + lane];
        float4 v2 = x4[s2 * 32 + lane];
        float4 v3 = x4[s3 * 32 + lane];
        acc.x += v0.x + v1.x + v2.x + v3.x;
        acc.y += v0.y + v1.y + v2.y + v3.y;
        acc.z += v0.z + v1.z + v2.z + v3.z;
        acc.w += v0.w + v1.w + v2.w + v3.w;
    }
    for (; e < e1; e++) {
        int s = g_srcidx[e];
        float4 v = x4[s * 32 + lane];
        acc.x += v.x; acc.y += v.y; acc.z += v.z; acc.w += v.w;
    }
    float vv[4] = {acc.x, acc.y, acc.z, acc.w};
    unsigned short h[4], l[4];
#pragma unroll
    for (int i = 0; i < 4; i++) split_bf(vv[i], h[i], l[i]);
    uint2 hv = make_uint2((unsigned)h[0] | ((unsigned)h[1] << 16),
                          (unsigned)h[2] | ((unsigned)h[3] << 16));
    uint2 lv = make_uint2((unsigned)l[0] | ((unsigned)l[1] << 16),
                          (unsigned)l[2] | ((unsigned)l[3] << 16));
    ((uint2*)g_ahi)[node * 32 + lane] = hv;
    ((uint2*)g_alo)[node * 32 + lane] = lv;
}

// ---------------- tensor-core GEMM (bf16 hi/lo split, 4x2 warp tiling) -----
// out = relu(A[M,128] @ W[128,128] + b).
// mode 0: write bf16 hi/lo packed (feeds GEMM2).
// mode 1: NO dense output; fused BN stats + per-graph pooling sums (atomics).
#define SA_HI 0
#define SA_LO 34816
#define SW_HI 69632
#define SW_LO 104448
#define SBIAS 139264
#define SBATCH 139776
#define GEMM_SMEM 140288

__global__ __launch_bounds__(256, 1) void gemm_mma_kernel(
        const unsigned* __restrict__ Ahi, const unsigned* __restrict__ Alo,
        const float* __restrict__ W, const float* __restrict__ bias,
        unsigned* __restrict__ out_hi, unsigned* __restrict__ out_lo,
        const void* __restrict__ batch, int M, int mode) {
    extern __shared__ char smem[];
    uint32_t sbase = smem_u32(smem);
    float* sV = (float*)smem;                   // overlaps A region post-compute
    float* sBias = (float*)(smem + SBIAS);
    int* sB = (int*)(smem + SBATCH);
    unsigned* aHiW = (unsigned*)(smem + SA_HI); // rows of 68 uints
    unsigned* aLoW = (unsigned*)(smem + SA_LO);
    int t = threadIdx.x;
    int lane = t & 31;
    int w = t >> 5;
    int wr = w >> 1, wc = w & 1;
    int m0 = wr * 32, n0 = wc * 64;
    int is64 = g_is64;

    // split W -> smem hi/lo, once
    for (int idx = t; idx < 128 * 128; idx += 256) {
        int k = idx >> 7, n = idx & 127;
        unsigned short h, l;
        split_bf(W[idx], h, l);
        *(unsigned short*)(smem + SW_HI + (k * 136 + n) * 2) = h;
        *(unsigned short*)(smem + SW_LO + (k * 136 + n) * 2) = l;
    }
    if (t < 128) sBias[t] = bias[t];

    // ldmatrix per-lane address components
    int lrow = (lane & 7) + ((lane >> 3) & 1) * 8;
    int lcol = (lane >> 4) * 8;
    uint32_t aOff = (uint32_t)(lrow * 136 + lcol) * 2;
    uint32_t bOff = aOff;

    for (int tile = blockIdx.x; tile < NTILES; tile += gridDim.x) {
        int row0 = tile << 7;
        for (int idx = t; idx < 8192; idx += 256) {
            int r = idx >> 6, c2 = idx & 63;
            int gr = row0 + r;
            unsigned vh = 0, vl = 0;
            if (gr < M) { vh = Ahi[gr * 64 + c2]; vl = Alo[gr * 64 + c2]; }
            aHiW[r * 68 + c2] = vh;
            aLoW[r * 68 + c2] = vl;
        }
        __syncthreads();

        float c[2][8][4];
#pragma unroll
        for (int mh = 0; mh < 2; mh++)
#pragma unroll
            for (int j = 0; j < 8; j++)
#pragma unroll
                for (int q = 0; q < 4; q++) c[mh][j][q] = 0.f;

#pragma unroll 1
        for (int ks = 0; ks < 8; ks++) {
            uint32_t ah[2][4], al[2][4];
#pragma unroll
            for (int mh = 0; mh < 2; mh++) {
                uint32_t aa = sbase + SA_HI + (uint32_t)(m0 + mh * 16) * 272 +
                              (uint32_t)ks * 32 + aOff;
                ldsm_x4(ah[mh], aa);
                ldsm_x4(al[mh], aa + (SA_LO - SA_HI));
            }
#pragma unroll
            for (int nj = 0; nj < 4; nj++) {
                uint32_t bh[4], bl[4];
                uint32_t ba = sbase + SW_HI + (uint32_t)ks * 16 * 272 +
                              (uint32_t)(n0 + nj * 16) * 2 + bOff;
                ldsm_x4_t(bh, ba);
                ldsm_x4_t(bl, ba + (SW_LO - SW_HI));
#pragma unroll
                for (int mh = 0; mh < 2; mh++) {
                    mma_bf16(c[mh][2 * nj],     ah[mh], bh[0], bh[1]);
                    mma_bf16(c[mh][2 * nj + 1], ah[mh], bh[2], bh[3]);
                    mma_bf16(c[mh][2 * nj],     ah[mh], bl[0], bl[1]);
                    mma_bf16(c[mh][2 * nj + 1], ah[mh], bl[2], bl[3]);
                    mma_bf16(c[mh][2 * nj],     al[mh], bh[0], bh[1]);
                    mma_bf16(c[mh][2 * nj + 1], al[mh], bh[2], bh[3]);
                }
            }
        }
        __syncthreads();   // done reading A smem -> safe to write sV

        // epilogue: bias + relu -> sV
        int er = lane >> 2;
        int ec = 2 * (lane & 3);
#pragma unroll
        for (int mh = 0; mh < 2; mh++)
#pragma unroll
            for (int j = 0; j < 8; j++) {
                int n = n0 + j * 8 + ec;
                int rr = m0 + mh * 16 + er;
                float b0 = sBias[n], b1 = sBias[n + 1];
                float* cc = c[mh][j];
                *(float2*)&sV[rr * 132 + n] =
                    make_float2(fmaxf(cc[0] + b0, 0.f), fmaxf(cc[1] + b1, 0.f));
                *(float2*)&sV[(rr + 8) * 132 + n] =
                    make_float2(fmaxf(cc[2] + b0, 0.f), fmaxf(cc[3] + b1, 0.f));
            }
        __syncthreads();

        if (mode == 0) {
            for (int idx = t; idx < 128 * 64; idx += 256) {
                int r = idx >> 6, c2 = idx & 63;
                int gr = row0 + r;
                if (gr < M) {
                    float v0 = sV[r * 132 + c2 * 2];
                    float v1 = sV[r * 132 + c2 * 2 + 1];
                    unsigned short h0, l0, h1, l1;
                    split_bf(v0, h0, l0);
                    split_bf(v1, h1, l1);
                    out_hi[gr * 64 + c2] = (unsigned)h0 | ((unsigned)h1 << 16);
                    out_lo[gr * 64 + c2] = (unsigned)l0 | ((unsigned)l1 << 16);
                }
            }
        } else {
            // fused BN stats + per-graph pooling sums
            if (t < 128) {
                int gr = row0 + t;
                sB[t] = (gr < M) ? load_index(batch, gr, is64) : -1;
            }
            __syncthreads();
            if (t < 128) {
                float s = 0.f, q = 0.f;
                float run = 0.f;
                int cur = sB[0];
                for (int r = 0; r < 128; r++) {
                    int b = sB[r];
                    if (b != cur) {
                        if (cur >= 0) atomicAdd(&g_gsum[cur * NF + t], run);
                        run = 0.f;
                        cur = b;
                    }
                    if (b >= 0) {
                        float v = sV[r * 132 + t];
                        run += v;
                        s += v;
                        q += v * v;
                    }
                }
                if (cur >= 0) atomicAdd(&g_gsum[cur * NF + t], run);
                atomicAdd(&g_stats[t], s);
                atomicAdd(&g_stats[128 + t], q);
            }
        }
        __syncthreads();   // before next tile's A load overwrites sV
    }
}

// ---------------- fused: BN-affine pool + recurrence + output MLP ----------
// Block owns 4 graphs. xg = affine(gsum/cnt); 10 gated iterations in smem;
// then the 2-layer MLP straight to d_out.
#define WT_STRIDE 260
#define RECUR_SMEM ((128 * WT_STRIDE + 128 + 4 * 256 + 96 + 8) * (int)sizeof(float))

__global__ __launch_bounds__(128) void recur_mlp_kernel(
        const void* __restrict__ batch,
        const float* __restrict__ gamma, const float* __restrict__ beta,
        const float* __restrict__ Wl1, const float* __restrict__ bl1,
        const float* __restrict__ Wl2, const float* __restrict__ bl2,
        const float* __restrict__ Wm1, const float* __restrict__ bm1,
        const float* __restrict__ Wm2, const float* __restrict__ bm2,
        float* __restrict__ out) {
    extern __shared__ float sm[];
    float* Wt  = sm;                        // [128][260]
    float* bs  = Wt + 128 * WT_STRIDE;      // [128]
    float* cat = bs + 128;                  // [4][256]
    float* hid = cat + 4 * 256;             // [96]
    int* se = (int*)(hid + 96);             // [5]
    int t = threadIdx.x;
    int g0 = blockIdx.x * 4;
    int is64 = g_is64;

    // graph boundaries via binary search (batch sorted)
    if (t < 5) {
        int target = g0 + t;
        int lo = 0, hi = N_NODES;
        while (lo < hi) {
            int mid = (lo + hi) >> 1;
            int b = load_index(batch, mid, is64);
            if (b < target) lo = mid + 1; else hi = mid;
        }
        se[t] = lo;
    }

    // transpose-load recurrence weights
    for (int idx = t; idx < 256 * 64; idx += 128) {
        int k = idx >> 6, c = idx & 63;
        Wt[c * WT_STRIDE + k] = Wl2[idx];
        Wt[(c + 64) * WT_STRIDE + k] = Wl1[idx];
    }
    bs[t] = (t < 64) ? bl2[t] : bl1[t - 64];
    __syncthreads();

    // xg = BN-affine(mean) per graph, h init = xg
    float mu = g_stats[t] / (float)N_NODES;
    float var = g_stats[128 + t] / (float)N_NODES - mu * mu;
    float rs = rsqrtf(var + BN_EPS);
    float gm = gamma[t], bt = beta[t];
#pragma unroll
    for (int r = 0; r < 4; r++) {
        int cnt = se[r + 1] - se[r];
        float val = 0.f;
        if (cnt > 0) {
            float m = g_gsum[(g0 + r) * NF + t] / (float)cnt;
            val = gm * (m - mu) * rs + bt;
        }
        cat[r * 256 + t] = val;
        cat[r * 256 + 128 + t] = val;
    }
    __syncthreads();

    const float* w = &Wt[t * WT_STRIDE];
    float bias = bs[t];
    for (int it = 0; it < N_ITERS; it++) {
        float a0 = bias, a1 = bias, a2 = bias, a3 = bias;
#pragma unroll 8
        for (int k = 0; k < 256; k += 4) {
            float4 wv = *(const float4*)&w[k];
            float4 c0 = *(const float4*)&cat[0 * 256 + k];
            float4 c1 = *(const float4*)&cat[1 * 256 + k];
            float4 c2 = *(const float4*)&cat[2 * 256 + k];
            float4 c3 = *(const float4*)&cat[3 * 256 + k];
            a0 += c0.x * wv.x + c0.y * wv.y + c0.z * wv.z + c0.w * wv.w;
            a1 += c1.x * wv.x + c1.y * wv.y + c1.z * wv.z + c1.w * wv.w;
            a2 += c2.x * wv.x + c2.y * wv.y + c2.z * wv.z + c2.w * wv.w;
            a3 += c3.x * wv.x + c3.y * wv.y + c3.z * wv.z + c3.w * wv.w;
        }
        float o[4] = {a0, a1, a2, a3};
        float v[4];
#pragma unroll
        for (int r = 0; r < 4; r++)
            v[r] = (t < 64) ? tanhf(o[r]) : (1.0f / (1.0f + expf(-o[r])));
        __syncthreads();
#pragma unroll
        for (int r = 0; r < 4; r++) cat[r * 256 + 128 + t] = v[r];
        __syncthreads();
    }

    // output MLP per graph (h = cat[r][128..255])
    for (int r = 0; r < 4; r++) {
        if (t < DIM) {
            float a = bm1[t];
            const float* h = &cat[r * 256 + 128];
#pragma unroll 8
            for (int k = 0; k < NF; k++) a += h[k] * Wm1[k * DIM + t];
            hid[t] = fmaxf(a, 0.f);
        }
        __syncthreads();
        if (t < N_OUT) {
            float a = bm2[t];
            for (int k = 0; k < DIM; k++) a += hid[k] * Wm2[k * N_OUT + t];
            out[(g0 + r) * N_OUT + t] = a;
        }
        __syncthreads();
    }
}

// ---------------- host ----------------
extern "C" void kernel_launch(void* const* d_in, const int* in_sizes, int n_in,
                              void* d_out, int out_size) {
    const float* x     = (const float*)d_in[0];
    const void*  ei    = d_in[1];
    const void*  batch = d_in[2];
    const float* W1a = (const float*)d_in[3];
    const float* b1a = (const float*)d_in[4];
    const float* W1b = (const float*)d_in[5];
    const float* b1b = (const float*)d_in[6];
    const float* gamma = (const float*)d_in[7];
    const float* beta  = (const float*)d_in[8];
    const float* Wl1 = (const float*)d_in[9];
    const float* bl1 = (const float*)d_in[10];
    const float* Wl2 = (const float*)d_in[11];
    const float* bl2 = (const float*)d_in[12];
    const float* Wm1 = (const float*)d_in[13];
    const float* bm1 = (const float*)d_in[14];
    const float* Wm2 = (const float*)d_in[15];
    const float* bm2 = (const float*)d_in[16];
    float* out = (float*)d_out;

    void *p_ahi, *p_alo, *p_t1hi, *p_t1lo;
    cudaGetSymbolAddress(&p_ahi, g_ahi);
    cudaGetSymbolAddress(&p_alo, g_alo);
    cudaGetSymbolAddress(&p_t1hi, g_t1hi);
    cudaGetSymbolAddress(&p_t1lo, g_t1lo);

    cudaFuncSetAttribute(gemm_mma_kernel,
                         cudaFuncAttributeMaxDynamicSharedMemorySize, GEMM_SMEM);
    cudaFuncSetAttribute(recur_mlp_kernel,
                         cudaFuncAttributeMaxDynamicSharedMemorySize, RECUR_SMEM);

    init_kernel<<<SCAN_NBLK, 256>>>((const int*)ei);
    count_kernel<<<1024, 256>>>(ei);
    scanA_kernel<<<SCAN_NBLK, 256>>>();
    scanB_kernel<<<1, 256>>>();
    scanC_kernel<<<SCAN_NBLK, 256>>>();
    scatter_kernel<<<1024, 256>>>(ei);
    agg_kernel<<<(N_NODES + 7) / 8, 256>>>((const float4*)x);
    gemm_mma_kernel<<<148, 256, GEMM_SMEM>>>(
        (const unsigned*)p_ahi, (const unsigned*)p_alo, W1a, b1a,
        (unsigned*)p_t1hi, (unsigned*)p_t1lo, nullptr, N_NODES, 0);
    gemm_mma_kernel<<<148, 256, GEMM_SMEM>>>(
        (const unsigned*)p_t1hi, (const unsigned*)p_t1lo, W1b, b1b,
        nullptr, nullptr, batch, N_NODES, 1);
    recur_mlp_kernel<<<N_GRAPHS / 4, 128, RECUR_SMEM>>>(
        batch, gamma, beta, Wl1, bl1, Wl2, bl2, Wm1, bm1, Wm2, bm2, out);
}

// round 6
// speedup vs baseline: 2.5086x; 1.0838x over previous
#include <cuda_runtime.h>
#include <cuda_bf16.h>
#include <math.h>
#include <stdint.h>

#define N_NODES  50000
#define N_EDGES  600000
#define NF       128
#define N_GRAPHS 256
#define DIM      95
#define N_OUT    12
#define N_ITERS  10
#define BN_EPS   1e-5f
#define SCAN_NBLK 196
#define NTILES   391             // ceil(50000/128)

// ---------------- scratch (zero-initialized at load; self-cleaning) --------
__device__ unsigned g_ahi[N_NODES * 64];   // bf16x2 packed: (x+agg) hi
__device__ unsigned g_alo[N_NODES * 64];
__device__ unsigned g_t1hi[N_NODES * 64];
__device__ unsigned g_t1lo[N_NODES * 64];
__device__ int   g_counts[N_NODES];        // zeroed by scanAB after use
__device__ int   g_offsets[N_NODES + 1];   // block-local prefixes
__device__ int   g_cursor[N_NODES];
__device__ int   g_srcidx[N_EDGES];
__device__ int   g_bsums[SCAN_NBLK];
__device__ int   g_bpre[SCAN_NBLK];
__device__ float g_stats[2 * NF];          // zeroed by recur_mlp last block
__device__ float g_gsum[N_GRAPHS * NF];    // zeroed by its recur_mlp block
__device__ int   g_tickA;                  // self-resetting tickets
__device__ int   g_tickR;

// ---------------- helpers ----------------
__device__ __forceinline__ uint32_t smem_u32(const void* p) {
    uint32_t a;
    asm("{ .reg .u64 t; cvta.to.shared.u64 t, %1; cvt.u32.u64 %0, t; }" : "=r"(a) : "l"(p));
    return a;
}
__device__ __forceinline__ void split_bf(float v, unsigned short& h, unsigned short& l) {
    __nv_bfloat16 hb = __float2bfloat16(v);
    float r = v - __bfloat162float(hb);
    __nv_bfloat16 lb = __float2bfloat16(r);
    h = __bfloat16_as_ushort(hb);
    l = __bfloat16_as_ushort(lb);
}
__device__ __forceinline__ void ldsm_x4(uint32_t* r, uint32_t addr) {
    asm volatile("ldmatrix.sync.aligned.m8n8.x4.shared.b16 {%0,%1,%2,%3}, [%4];"
        : "=r"(r[0]), "=r"(r[1]), "=r"(r[2]), "=r"(r[3]) : "r"(addr));
}
__device__ __forceinline__ void ldsm_x4_t(uint32_t* r, uint32_t addr) {
    asm volatile("ldmatrix.sync.aligned.m8n8.x4.trans.shared.b16 {%0,%1,%2,%3}, [%4];"
        : "=r"(r[0]), "=r"(r[1]), "=r"(r[2]), "=r"(r[3]) : "r"(addr));
}
__device__ __forceinline__ void mma_bf16(float* c, const uint32_t* a,
                                         uint32_t b0, uint32_t b1) {
    asm volatile("mma.sync.aligned.m16n8k16.row.col.f32.bf16.bf16.f32 "
        "{%0,%1,%2,%3}, {%4,%5,%6,%7}, {%8,%9}, {%0,%1,%2,%3};"
        : "+f"(c[0]), "+f"(c[1]), "+f"(c[2]), "+f"(c[3])
        : "r"(a[0]), "r"(a[1]), "r"(a[2]), "r"(a[3]), "r"(b0), "r"(b1));
}
__device__ __forceinline__ void cp_async16(uint32_t dst, const void* src, int srcsz) {
    asm volatile("cp.async.cg.shared.global [%0], [%1], 16, %2;"
        :: "r"(dst), "l"(src), "r"(srcsz) : "memory");
}
#define CP_COMMIT() asm volatile("cp.async.commit_group;" ::: "memory")
#define CP_WAIT1()  asm volatile("cp.async.wait_group 1;" ::: "memory")
__device__ __forceinline__ int load_index(const void* p, long long i, int is64) {
    if (is64) return (int)((const long long*)p)[i];
    return ((const int*)p)[i];
}
// Block-local dtype probe: for int64 data the odd 32-bit words of the first
// 2048 words are all zero; for int32 they are real (nonzero) values.
__device__ __forceinline__ int probe_is64(const void* p) {
    const int* w32 = (const int*)p;
    int bad = 0;
    for (int j = threadIdx.x; j < 1024; j += blockDim.x)
        if (w32[2 * j + 1] != 0) bad = 1;
    return !__syncthreads_or(bad);
}

// ---------------- CSR: count ----------------
__global__ void count_kernel(const void* ei) {
    int is64 = probe_is64(ei);
    for (int e = blockIdx.x * blockDim.x + threadIdx.x; e < N_EDGES;
         e += gridDim.x * blockDim.x) {
        int d = load_index(ei, (long long)N_EDGES + e, is64);
        atomicAdd(&g_counts[d], 1);
    }
}

// ---------------- fused scan (local prefix + last-block scans block sums) --
__global__ void scanAB_kernel() {
    __shared__ int ws[8];
    __shared__ int amLast;
    int t = threadIdx.x, lane = t & 31, w = t >> 5;
    int i = blockIdx.x * 256 + t;
    int v = (i < N_NODES) ? g_counts[i] : 0;
    if (i < N_NODES) g_counts[i] = 0;          // self-clean for next call
    int x = v;
#pragma unroll
    for (int o = 1; o < 32; o <<= 1) {
        int y = __shfl_up_sync(0xffffffffu, x, o);
        if (lane >= o) x += y;
    }
    if (lane == 31) ws[w] = x;
    __syncthreads();
    if (w == 0) {
        int y = (lane < 8) ? ws[lane] : 0;
#pragma unroll
        for (int o = 1; o < 32; o <<= 1) {
            int z = __shfl_up_sync(0xffffffffu, y, o);
            if (lane >= o) y += z;
        }
        if (lane < 8) ws[lane] = y;
    }
    __syncthreads();
    int pre = ((w > 0) ? ws[w - 1] : 0) + x - v;  // block-local exclusive
    if (i <= N_NODES) g_offsets[i] = pre;
    if (i < N_NODES) g_cursor[i] = pre;
    if (t == 255) g_bsums[blockIdx.x] = ws[7];

    if (t == 0) {
        __threadfence();
        int k = atomicAdd(&g_tickA, 1);
        amLast = (k == SCAN_NBLK - 1);
        if (amLast) __threadfence();
    }
    __syncthreads();
    if (amLast) {
        int v2 = (t < SCAN_NBLK) ? g_bsums[t] : 0;
        int x2 = v2;
#pragma unroll
        for (int o = 1; o < 32; o <<= 1) {
            int y = __shfl_up_sync(0xffffffffu, x2, o);
            if (lane >= o) x2 += y;
        }
        __syncthreads();
        if (lane == 31) ws[w] = x2;
        __syncthreads();
        if (w == 0) {
            int y = (lane < 8) ? ws[lane] : 0;
#pragma unroll
            for (int o = 1; o < 32; o <<= 1) {
                int z = __shfl_up_sync(0xffffffffu, y, o);
                if (lane >= o) y += z;
            }
            if (lane < 8) ws[lane] = y;
        }
        __syncthreads();
        if (t < SCAN_NBLK) g_bpre[t] = ((w > 0) ? ws[w - 1] : 0) + x2 - v2;
        if (t == 0) g_tickA = 0;               // self-reset ticket
    }
}

// ---------------- CSR: scatter (bpre added at use) ----------------
__global__ void scatter_kernel(const void* ei) {
    int is64 = probe_is64(ei);
    for (int e = blockIdx.x * blockDim.x + threadIdx.x; e < N_EDGES;
         e += gridDim.x * blockDim.x) {
        int s = load_index(ei, e, is64);
        int d = load_index(ei, (long long)N_EDGES + e, is64);
        int pos = g_bpre[d >> 8] + atomicAdd(&g_cursor[d], 1);
        g_srcidx[pos] = s;
    }
}

// ---------------- GIN aggregation -> bf16 hi/lo ----------------
__global__ void agg_kernel(const float4* __restrict__ x4) {
    int node = blockIdx.x * 8 + (threadIdx.x >> 5);
    int lane = threadIdx.x & 31;
    if (node >= N_NODES) return;
    float4 acc = x4[node * 32 + lane];
    int e0 = g_offsets[node] + g_bpre[node >> 8];
    int e1 = g_offsets[node + 1] + g_bpre[(node + 1) >> 8];
    int e = e0;
    int n4 = e0 + ((e1 - e0) & ~3);
    for (; e < n4; e += 4) {
        int s0 = g_srcidx[e], s1 = g_srcidx[e + 1];
        int s2 = g_srcidx[e + 2], s3 = g_srcidx[e + 3];
        float4 v0 = x4[s0 * 32 + lane];
        float4 v1 = x4[s1 * 32 + lane];
        float4 v2 = x4[s2 * 32 + lane];
        float4 v3 = x4[s3 * 32 + lane];
        acc.x += v0.x + v1.x + v2.x + v3.x;
        acc.y += v0.y + v1.y + v2.y + v3.y;
        acc.z += v0.z + v1.z + v2.z + v3.z;
        acc.w += v0.w + v1.w + v2.w + v3.w;
    }
    for (; e < e1; e++) {
        int s = g_srcidx[e];
        float4 v = x4[s * 32 + lane];
        acc.x += v.x; acc.y += v.y; acc.z += v.z; acc.w += v.w;
    }
    float vv[4] = {acc.x, acc.y, acc.z, acc.w};
    unsigned short h[4], l[4];
#pragma unroll
    for (int i = 0; i < 4; i++) split_bf(vv[i], h[i], l[i]);
    uint2 hv = make_uint2((unsigned)h[0] | ((unsigned)h[1] << 16),
                          (unsigned)h[2] | ((unsigned)h[3] << 16));
    uint2 lv = make_uint2((unsigned)l[0] | ((unsigned)l[1] << 16),
                          (unsigned)l[2] | ((unsigned)l[3] << 16));
    ((uint2*)g_ahi)[node * 32 + lane] = hv;
    ((uint2*)g_alo)[node * 32 + lane] = lv;
}

// ---------------- tensor-core GEMM, cp.async double-buffered ---------------
// out = relu(A[M,128] @ W[128,128] + b), bf16 hi/lo split (3 terms).
// mode 0: bf16 hi/lo packed output straight from registers.
// mode 1: fused BN stats + per-graph pooling sums (uses sV in current buffer).
#define SA0   0
#define SA1   69632
#define ALO_OFF 34816
#define SW_HI 139264
#define SW_LO 174080
#define SBIAS 208896
#define SBATCH 209408
#define GEMM_SMEM 209920

__global__ __launch_bounds__(256, 1) void gemm_mma_kernel(
        const unsigned* __restrict__ Ahi, const unsigned* __restrict__ Alo,
        const float* __restrict__ W, const float* __restrict__ bias,
        unsigned* __restrict__ out_hi, unsigned* __restrict__ out_lo,
        const void* __restrict__ batch, int M, int mode) {
    extern __shared__ char smem[];
    uint32_t sbase = smem_u32(smem);
    float* sBias = (float*)(smem + SBIAS);
    int* sB = (int*)(smem + SBATCH);
    int t = threadIdx.x;
    int lane = t & 31;
    int w = t >> 5;
    int wr = w >> 1, wc = w & 1;
    int m0 = wr * 32, n0 = wc * 64;
    int is64 = (mode == 1) ? probe_is64(batch) : 0;

    // prologue: prefetch first tile into buffer 0
    {
        int tile0 = blockIdx.x;
        if (tile0 < NTILES) {
            int row0 = tile0 << 7;
            for (int idx = t; idx < 2048; idx += 256) {
                int r = idx >> 4, c4 = idx & 15;
                int gr = row0 + r;
                int ok = (gr < M) ? 16 : 0;
                int grc = ok ? gr : 0;
                cp_async16(sbase + SA0 + r * 272 + c4 * 16, Ahi + grc * 64 + c4 * 4, ok);
                cp_async16(sbase + SA0 + ALO_OFF + r * 272 + c4 * 16,
                           Alo + grc * 64 + c4 * 4, ok);
            }
        }
        CP_COMMIT();
    }

    // split W -> smem hi/lo (overlaps prologue prefetch)
    for (int idx = t; idx < 128 * 128; idx += 256) {
        int k = idx >> 7, n = idx & 127;
        unsigned short h, l;
        split_bf(W[idx], h, l);
        *(unsigned short*)(smem + SW_HI + (k * 136 + n) * 2) = h;
        *(unsigned short*)(smem + SW_LO + (k * 136 + n) * 2) = l;
    }
    if (t < 128) sBias[t] = bias[t];

    int lrow = (lane & 7) + ((lane >> 3) & 1) * 8;
    int lcol = (lane >> 4) * 8;
    uint32_t lOff = (uint32_t)(lrow * 136 + lcol) * 2;

    int buf = 0;
    for (int tile = blockIdx.x; tile < NTILES; tile += gridDim.x) {
        int row0 = tile << 7;
        // prefetch next tile into the other buffer
        {
            int nt = tile + gridDim.x;
            uint32_t nb = (buf ^ 1) ? SA1 : SA0;
            if (nt < NTILES) {
                int row0n = nt << 7;
                for (int idx = t; idx < 2048; idx += 256) {
                    int r = idx >> 4, c4 = idx & 15;
                    int gr = row0n + r;
                    int ok = (gr < M) ? 16 : 0;
                    int grc = ok ? gr : 0;
                    cp_async16(sbase + nb + r * 272 + c4 * 16,
                               Ahi + grc * 64 + c4 * 4, ok);
                    cp_async16(sbase + nb + ALO_OFF + r * 272 + c4 * 16,
                               Alo + grc * 64 + c4 * 4, ok);
                }
            }
            CP_COMMIT();
        }
        CP_WAIT1();          // current tile's data ready
        __syncthreads();

        uint32_t cb = buf ? SA1 : SA0;

        float c[2][8][4];
#pragma unroll
        for (int mh = 0; mh < 2; mh++)
#pragma unroll
            for (int j = 0; j < 8; j++)
#pragma unroll
                for (int q = 0; q < 4; q++) c[mh][j][q] = 0.f;

#pragma unroll 1
        for (int ks = 0; ks < 8; ks++) {
            uint32_t ah[2][4], al[2][4];
#pragma unroll
            for (int mh = 0; mh < 2; mh++) {
                uint32_t aa = sbase + cb + (uint32_t)(m0 + mh * 16) * 272 +
                              (uint32_t)ks * 32 + lOff;
                ldsm_x4(ah[mh], aa);
                ldsm_x4(al[mh], aa + ALO_OFF);
            }
#pragma unroll
            for (int nj = 0; nj < 4; nj++) {
                uint32_t bh[4], bl[4];
                uint32_t ba = sbase + SW_HI + (uint32_t)ks * 16 * 272 +
                              (uint32_t)(n0 + nj * 16) * 2 + lOff;
                ldsm_x4_t(bh, ba);
                ldsm_x4_t(bl, ba + (SW_LO - SW_HI));
#pragma unroll
                for (int mh = 0; mh < 2; mh++) {
                    mma_bf16(c[mh][2 * nj],     ah[mh], bh[0], bh[1]);
                    mma_bf16(c[mh][2 * nj + 1], ah[mh], bh[2], bh[3]);
                    mma_bf16(c[mh][2 * nj],     ah[mh], bl[0], bl[1]);
                    mma_bf16(c[mh][2 * nj + 1], ah[mh], bl[2], bl[3]);
                    mma_bf16(c[mh][2 * nj],     al[mh], bh[0], bh[1]);
                    mma_bf16(c[mh][2 * nj + 1], al[mh], bh[2], bh[3]);
                }
            }
        }

        if (mode == 0) {
            // register epilogue: bias+relu, split to bf16 hi/lo, store packed
            int er = lane >> 2;
            int ec = 2 * (lane & 3);
#pragma unroll
            for (int mh = 0; mh < 2; mh++)
#pragma unroll
                for (int j = 0; j < 8; j++) {
                    int n = n0 + j * 8 + ec;
                    float b0 = sBias[n], b1 = sBias[n + 1];
                    float* cc = c[mh][j];
                    int gr0 = row0 + m0 + mh * 16 + er;
                    if (gr0 < M) {
                        unsigned short h0, l0, h1, l1;
                        split_bf(fmaxf(cc[0] + b0, 0.f), h0, l0);
                        split_bf(fmaxf(cc[1] + b1, 0.f), h1, l1);
                        out_hi[gr0 * 64 + (n >> 1)] = (unsigned)h0 | ((unsigned)h1 << 16);
                        out_lo[gr0 * 64 + (n >> 1)] = (unsigned)l0 | ((unsigned)l1 << 16);
                    }
                    int gr1 = gr0 + 8;
                    if (gr1 < M) {
                        unsigned short h2, l2, h3, l3;
                        split_bf(fmaxf(cc[2] + b0, 0.f), h2, l2);
                        split_bf(fmaxf(cc[3] + b1, 0.f), h3, l3);
                        out_hi[gr1 * 64 + (n >> 1)] = (unsigned)h2 | ((unsigned)h3 << 16);
                        out_lo[gr1 * 64 + (n >> 1)] = (unsigned)l2 | ((unsigned)l3 << 16);
                    }
                }
            __syncthreads();   // protect current buffer from next prefetch
        } else {
            __syncthreads();   // all warps done reading A smem
            float* sV = (float*)(smem + cb);   // reuse consumed buffer
            int er = lane >> 2;
            int ec = 2 * (lane & 3);
#pragma unroll
            for (int mh = 0; mh < 2; mh++)
#pragma unroll
                for (int j = 0; j < 8; j++) {
                    int n = n0 + j * 8 + ec;
                    int rr = m0 + mh * 16 + er;
                    float b0 = sBias[n], b1 = sBias[n + 1];
                    float* cc = c[mh][j];
                    *(float2*)&sV[rr * 132 + n] =
                        make_float2(fmaxf(cc[0] + b0, 0.f), fmaxf(cc[1] + b1, 0.f));
                    *(float2*)&sV[(rr + 8) * 132 + n] =
                        make_float2(fmaxf(cc[2] + b0, 0.f), fmaxf(cc[3] + b1, 0.f));
                }
            if (t < 128) {
                int gr = row0 + t;
                sB[t] = (gr < M) ? load_index(batch, gr, is64) : -1;
            }
            __syncthreads();
            if (t < 128) {
                float s = 0.f, q = 0.f, run = 0.f;
                int cur = sB[0];
                for (int r = 0; r < 128; r++) {
                    int b = sB[r];
                    if (b != cur) {
                        if (cur >= 0) atomicAdd(&g_gsum[cur * NF + t], run);
                        run = 0.f;
                        cur = b;
                    }
                    if (b >= 0) {
                        float v = sV[r * 132 + t];
                        run += v;
                        s += v;
                        q += v * v;
                    }
                }
                if (cur >= 0) atomicAdd(&g_gsum[cur * NF + t], run);
                atomicAdd(&g_stats[t], s);
                atomicAdd(&g_stats[128 + t], q);
            }
            __syncthreads();   // sV reads done before next prefetch overwrite
        }
        buf ^= 1;
    }
}

// ---------------- fused: BN-affine pool + recurrence + output MLP ----------
#define WT_STRIDE 260
#define RECUR_SMEM ((128 * WT_STRIDE + 128 + 4 * 256 + 96 + 8) * (int)sizeof(float))

__global__ __launch_bounds__(128) void recur_mlp_kernel(
        const void* __restrict__ batch,
        const float* __restrict__ gamma, const float* __restrict__ beta,
        const float* __restrict__ Wl1, const float* __restrict__ bl1,
        const float* __restrict__ Wl2, const float* __restrict__ bl2,
        const float* __restrict__ Wm1, const float* __restrict__ bm1,
        const float* __restrict__ Wm2, const float* __restrict__ bm2,
        float* __restrict__ out) {
    extern __shared__ float sm[];
    float* Wt  = sm;                        // [128][260]
    float* bs  = Wt + 128 * WT_STRIDE;      // [128]
    float* cat = bs + 128;                  // [4][256]
    float* hid = cat + 4 * 256;             // [96]
    int* se = (int*)(hid + 96);             // [5] + lastflag
    int t = threadIdx.x;
    int g0 = blockIdx.x * 4;
    int is64 = probe_is64(batch);

    if (t < 5) {
        int target = g0 + t;
        int lo = 0, hi = N_NODES;
        while (lo < hi) {
            int mid = (lo + hi) >> 1;
            int b = load_index(batch, mid, is64);
            if (b < target) lo = mid + 1; else hi = mid;
        }
        se[t] = lo;
    }

    for (int idx = t; idx < 256 * 64; idx += 128) {
        int k = idx >> 6, c = idx & 63;
        Wt[c * WT_STRIDE + k] = Wl2[idx];
        Wt[(c + 64) * WT_STRIDE + k] = Wl1[idx];
    }
    bs[t] = (t < 64) ? bl2[t] : bl1[t - 64];

    // read stats (then participate in ticketed zeroing)
    float st0 = g_stats[t];
    float st1 = g_stats[128 + t];
    float gs[4];
#pragma unroll
    for (int r = 0; r < 4; r++) {
        gs[r] = g_gsum[(g0 + r) * NF + t];
        g_gsum[(g0 + r) * NF + t] = 0.f;    // exclusive slice: self-clean
    }
    __syncthreads();
    if (t == 0) {
        __threadfence();
        int k = atomicAdd(&g_tickR, 1);
        se[5] = (k == N_GRAPHS / 4 - 1);
    }
    __syncthreads();
    if (se[5]) {
        g_stats[t] = 0.f;
        g_stats[128 + t] = 0.f;
        if (t == 0) g_tickR = 0;
    }

    float mu = st0 / (float)N_NODES;
    float var = st1 / (float)N_NODES - mu * mu;
    float rs = rsqrtf(var + BN_EPS);
    float gm = gamma[t], bt = beta[t];
#pragma unroll
    for (int r = 0; r < 4; r++) {
        int cnt = se[r + 1] - se[r];
        float val = 0.f;
        if (cnt > 0) {
            float m = gs[r] / (float)cnt;
            val = gm * (m - mu) * rs + bt;
        }
        cat[r * 256 + t] = val;
        cat[r * 256 + 128 + t] = val;
    }
    __syncthreads();

    const float* wv0 = &Wt[t * WT_STRIDE];
    float bias = bs[t];
    for (int it = 0; it < N_ITERS; it++) {
        float a0 = bias, a1 = bias, a2 = bias, a3 = bias;
#pragma unroll 8
        for (int k = 0; k < 256; k += 4) {
            float4 wv = *(const float4*)&wv0[k];
            float4 c0 = *(const float4*)&cat[0 * 256 + k];
            float4 c1 = *(const float4*)&cat[1 * 256 + k];
            float4 c2 = *(const float4*)&cat[2 * 256 + k];
            float4 c3 = *(const float4*)&cat[3 * 256 + k];
            a0 += c0.x * wv.x + c0.y * wv.y + c0.z * wv.z + c0.w * wv.w;
            a1 += c1.x * wv.x + c1.y * wv.y + c1.z * wv.z + c1.w * wv.w;
            a2 += c2.x * wv.x + c2.y * wv.y + c2.z * wv.z + c2.w * wv.w;
            a3 += c3.x * wv.x + c3.y * wv.y + c3.z * wv.z + c3.w * wv.w;
        }
        float o[4] = {a0, a1, a2, a3};
        float v[4];
#pragma unroll
        for (int r = 0; r < 4; r++)
            v[r] = (t < 64) ? tanhf(o[r]) : (1.0f / (1.0f + expf(-o[r])));
        __syncthreads();
#pragma unroll
        for (int r = 0; r < 4; r++) cat[r * 256 + 128 + t] = v[r];
        __syncthreads();
    }

    for (int r = 0; r < 4; r++) {
        if (t < DIM) {
            float a = bm1[t];
            const float* h = &cat[r * 256 + 128];
#pragma unroll 8
            for (int k = 0; k < NF; k++) a += h[k] * Wm1[k * DIM + t];
            hid[t] = fmaxf(a, 0.f);
        }
        __syncthreads();
        if (t < N_OUT) {
            float a = bm2[t];
            for (int k = 0; k < DIM; k++) a += hid[k] * Wm2[k * N_OUT + t];
            out[(g0 + r) * N_OUT + t] = a;
        }
        __syncthreads();
    }
}

// ---------------- host ----------------
extern "C" void kernel_launch(void* const* d_in, const int* in_sizes, int n_in,
                              void* d_out, int out_size) {
    const float* x     = (const float*)d_in[0];
    const void*  ei    = d_in[1];
    const void*  batch = d_in[2];
    const float* W1a = (const float*)d_in[3];
    const float* b1a = (const float*)d_in[4];
    const float* W1b = (const float*)d_in[5];
    const float* b1b = (const float*)d_in[6];
    const float* gamma = (const float*)d_in[7];
    const float* beta  = (const float*)d_in[8];
    const float* Wl1 = (const float*)d_in[9];
    const float* bl1 = (const float*)d_in[10];
    const float* Wl2 = (const float*)d_in[11];
    const float* bl2 = (const float*)d_in[12];
    const float* Wm1 = (const float*)d_in[13];
    const float* bm1 = (const float*)d_in[14];
    const float* Wm2 = (const float*)d_in[15];
    const float* bm2 = (const float*)d_in[16];
    float* out = (float*)d_out;

    void *p_ahi, *p_alo, *p_t1hi, *p_t1lo;
    cudaGetSymbolAddress(&p_ahi, g_ahi);
    cudaGetSymbolAddress(&p_alo, g_alo);
    cudaGetSymbolAddress(&p_t1hi, g_t1hi);
    cudaGetSymbolAddress(&p_t1lo, g_t1lo);

    cudaFuncSetAttribute(gemm_mma_kernel,
                         cudaFuncAttributeMaxDynamicSharedMemorySize, GEMM_SMEM);
    cudaFuncSetAttribute(recur_mlp_kernel,
                         cudaFuncAttributeMaxDynamicSharedMemorySize, RECUR_SMEM);

    count_kernel<<<512, 256>>>(ei);
    scanAB_kernel<<<SCAN_NBLK, 256>>>();
    scatter_kernel<<<512, 256>>>(ei);
    agg_kernel<<<(N_NODES + 7) / 8, 256>>>((const float4*)x);
    gemm_mma_kernel<<<148, 256, GEMM_SMEM>>>(
        (const unsigned*)p_ahi, (const unsigned*)p_alo, W1a, b1a,
        (unsigned*)p_t1hi, (unsigned*)p_t1lo, nullptr, N_NODES, 0);
    gemm_mma_kernel<<<148, 256, GEMM_SMEM>>>(
        (const unsigned*)p_t1hi, (const unsigned*)p_t1lo, W1b, b1b,
        nullptr, nullptr, batch, N_NODES, 1);
    recur_mlp_kernel<<<N_GRAPHS / 4, 128, RECUR_SMEM>>>(
        batch, gamma, beta, Wl1, bl1, Wl2, bl2, Wm1, bm1, Wm2, bm2, out);
}

// round 7
// speedup vs baseline: 3.1120x; 1.2405x over previous
#include <cuda_runtime.h>
#include <cuda_bf16.h>
#include <math.h>
#include <stdint.h>

#define N_NODES  50000
#define N_EDGES  600000
#define NF       128
#define N_GRAPHS 256
#define DIM      95
#define N_OUT    12
#define N_ITERS  10
#define BN_EPS   1e-5f
#define SCAN_NBLK 196
#define NTILES   391             // ceil(50000/128)

// ---------------- scratch (zero-initialized at load; self-cleaning) --------
__device__ unsigned g_ahi[N_NODES * 64];   // bf16x2 packed: (x+agg) hi
__device__ unsigned g_alo[N_NODES * 64];
__device__ int   g_counts[N_NODES];        // zeroed by scanAB after use
__device__ int   g_offsets[N_NODES + 1];   // block-local prefixes
__device__ int   g_cursor[N_NODES];
__device__ int   g_srcidx[N_EDGES];
__device__ int   g_bsums[SCAN_NBLK];
__device__ int   g_bpre[SCAN_NBLK];
__device__ float g_stats[2 * NF];          // zeroed by recur_mlp last block
__device__ float g_gsum[N_GRAPHS * NF];    // zeroed by its recur_mlp block
__device__ int   g_tickA;                  // self-resetting tickets
__device__ int   g_tickR;

// ---------------- helpers ----------------
__device__ __forceinline__ uint32_t smem_u32(const void* p) {
    uint32_t a;
    asm("{ .reg .u64 t; cvta.to.shared.u64 t, %1; cvt.u32.u64 %0, t; }" : "=r"(a) : "l"(p));
    return a;
}
__device__ __forceinline__ void split_bf(float v, unsigned short& h, unsigned short& l) {
    __nv_bfloat16 hb = __float2bfloat16(v);
    float r = v - __bfloat162float(hb);
    __nv_bfloat16 lb = __float2bfloat16(r);
    h = __bfloat16_as_ushort(hb);
    l = __bfloat16_as_ushort(lb);
}
__device__ __forceinline__ void ldsm_x4(uint32_t* r, uint32_t addr) {
    asm volatile("ldmatrix.sync.aligned.m8n8.x4.shared.b16 {%0,%1,%2,%3}, [%4];"
        : "=r"(r[0]), "=r"(r[1]), "=r"(r[2]), "=r"(r[3]) : "r"(addr));
}
__device__ __forceinline__ void ldsm_x4_t(uint32_t* r, uint32_t addr) {
    asm volatile("ldmatrix.sync.aligned.m8n8.x4.trans.shared.b16 {%0,%1,%2,%3}, [%4];"
        : "=r"(r[0]), "=r"(r[1]), "=r"(r[2]), "=r"(r[3]) : "r"(addr));
}
__device__ __forceinline__ void mma_bf16(float* c, const uint32_t* a,
                                         uint32_t b0, uint32_t b1) {
    asm volatile("mma.sync.aligned.m16n8k16.row.col.f32.bf16.bf16.f32 "
        "{%0,%1,%2,%3}, {%4,%5,%6,%7}, {%8,%9}, {%0,%1,%2,%3};"
        : "+f"(c[0]), "+f"(c[1]), "+f"(c[2]), "+f"(c[3])
        : "r"(a[0]), "r"(a[1]), "r"(a[2]), "r"(a[3]), "r"(b0), "r"(b1));
}
__device__ __forceinline__ void cp_async16(uint32_t dst, const void* src, int srcsz) {
    asm volatile("cp.async.cg.shared.global [%0], [%1], 16, %2;"
        :: "r"(dst), "l"(src), "r"(srcsz) : "memory");
}
#define CP_COMMIT() asm volatile("cp.async.commit_group;" ::: "memory")
#define CP_WAIT0()  asm volatile("cp.async.wait_group 0;" ::: "memory")
__device__ __forceinline__ int load_index(const void* p, long long i, int is64) {
    if (is64) return (int)((const long long*)p)[i];
    return ((const int*)p)[i];
}
// Block-local dtype probe: for int64 data the odd 32-bit words of the first
// 2048 words are all zero; for int32 they are real (nonzero) values.
__device__ __forceinline__ int probe_is64(const void* p) {
    const int* w32 = (const int*)p;
    int bad = 0;
    for (int j = threadIdx.x; j < 1024; j += blockDim.x)
        if (w32[2 * j + 1] != 0) bad = 1;
    return !__syncthreads_or(bad);
}

// ---------------- CSR: count ----------------
__global__ void count_kernel(const void* ei) {
    int is64 = probe_is64(ei);
    for (int e = blockIdx.x * blockDim.x + threadIdx.x; e < N_EDGES;
         e += gridDim.x * blockDim.x) {
        int d = load_index(ei, (long long)N_EDGES + e, is64);
        atomicAdd(&g_counts[d], 1);
    }
}

// ---------------- fused scan (local prefix + last-block scans block sums) --
__global__ void scanAB_kernel() {
    __shared__ int ws[8];
    __shared__ int amLast;
    int t = threadIdx.x, lane = t & 31, w = t >> 5;
    int i = blockIdx.x * 256 + t;
    int v = (i < N_NODES) ? g_counts[i] : 0;
    if (i < N_NODES) g_counts[i] = 0;          // self-clean for next call
    int x = v;
#pragma unroll
    for (int o = 1; o < 32; o <<= 1) {
        int y = __shfl_up_sync(0xffffffffu, x, o);
        if (lane >= o) x += y;
    }
    if (lane == 31) ws[w] = x;
    __syncthreads();
    if (w == 0) {
        int y = (lane < 8) ? ws[lane] : 0;
#pragma unroll
        for (int o = 1; o < 32; o <<= 1) {
            int z = __shfl_up_sync(0xffffffffu, y, o);
            if (lane >= o) y += z;
        }
        if (lane < 8) ws[lane] = y;
    }
    __syncthreads();
    int pre = ((w > 0) ? ws[w - 1] : 0) + x - v;  // block-local exclusive
    if (i <= N_NODES) g_offsets[i] = pre;
    if (i < N_NODES) g_cursor[i] = pre;
    if (t == 255) g_bsums[blockIdx.x] = ws[7];

    if (t == 0) {
        __threadfence();
        int k = atomicAdd(&g_tickA, 1);
        amLast = (k == SCAN_NBLK - 1);
        if (amLast) __threadfence();
    }
    __syncthreads();
    if (amLast) {
        int v2 = (t < SCAN_NBLK) ? g_bsums[t] : 0;
        int x2 = v2;
#pragma unroll
        for (int o = 1; o < 32; o <<= 1) {
            int y = __shfl_up_sync(0xffffffffu, x2, o);
            if (lane >= o) x2 += y;
        }
        __syncthreads();
        if (lane == 31) ws[w] = x2;
        __syncthreads();
        if (w == 0) {
            int y = (lane < 8) ? ws[lane] : 0;
#pragma unroll
            for (int o = 1; o < 32; o <<= 1) {
                int z = __shfl_up_sync(0xffffffffu, y, o);
                if (lane >= o) y += z;
            }
            if (lane < 8) ws[lane] = y;
        }
        __syncthreads();
        if (t < SCAN_NBLK) g_bpre[t] = ((w > 0) ? ws[w - 1] : 0) + x2 - v2;
        if (t == 0) g_tickA = 0;               // self-reset ticket
    }
}

// ---------------- CSR: scatter (bpre added at use) ----------------
__global__ void scatter_kernel(const void* ei) {
    int is64 = probe_is64(ei);
    for (int e = blockIdx.x * blockDim.x + threadIdx.x; e < N_EDGES;
         e += gridDim.x * blockDim.x) {
        int s = load_index(ei, e, is64);
        int d = load_index(ei, (long long)N_EDGES + e, is64);
        int pos = g_bpre[d >> 8] + atomicAdd(&g_cursor[d], 1);
        g_srcidx[pos] = s;
    }
}

// ---------------- GIN aggregation -> bf16 hi/lo ----------------
__global__ void agg_kernel(const float4* __restrict__ x4) {
    int node = blockIdx.x * 8 + (threadIdx.x >> 5);
    int lane = threadIdx.x & 31;
    if (node >= N_NODES) return;
    float4 acc = x4[node * 32 + lane];
    int e0 = g_offsets[node] + g_bpre[node >> 8];
    int e1 = g_offsets[node + 1] + g_bpre[(node + 1) >> 8];
    int e = e0;
    int n4 = e0 + ((e1 - e0) & ~3);
    for (; e < n4; e += 4) {
        int s0 = g_srcidx[e], s1 = g_srcidx[e + 1];
        int s2 = g_srcidx[e + 2], s3 = g_srcidx[e + 3];
        float4 v0 = x4[s0 * 32 + lane];
        float4 v1 = x4[s1 * 32 + lane];
        float4 v2 = x4[s2 * 32 + lane];
        float4 v3 = x4[s3 * 32 + lane];
        acc.x += v0.x + v1.x + v2.x + v3.x;
        acc.y += v0.y + v1.y + v2.y + v3.y;
        acc.z += v0.z + v1.z + v2.z + v3.z;
        acc.w += v0.w + v1.w + v2.w + v3.w;
    }
    for (; e < e1; e++) {
        int s = g_srcidx[e];
        float4 v = x4[s * 32 + lane];
        acc.x += v.x; acc.y += v.y; acc.z += v.z; acc.w += v.w;
    }
    float vv[4] = {acc.x, acc.y, acc.z, acc.w};
    unsigned short h[4], l[4];
#pragma unroll
    for (int i = 0; i < 4; i++) split_bf(vv[i], h[i], l[i]);
    uint2 hv = make_uint2((unsigned)h[0] | ((unsigned)h[1] << 16),
                          (unsigned)h[2] | ((unsigned)h[3] << 16));
    uint2 lv = make_uint2((unsigned)l[0] | ((unsigned)l[1] << 16),
                          (unsigned)l[2] | ((unsigned)l[3] << 16));
    ((uint2*)g_ahi)[node * 32 + lane] = hv;
    ((uint2*)g_alo)[node * 32 + lane] = lv;
}

// ---------------- fused dual GEMM (nn1 both layers) ------------------------
// x1 = relu(relu(A@W1a + b1a)@W1b + b1b), A given as bf16 hi/lo.
// t1 (intermediate) lives only in smem (written back into the A buffer).
// Epilogue 2: fused BN stats + per-graph pooling sums. No dense output.
#define SA      0                 /* A/t1 tile: hi @ +0, lo @ +34816 */
#define ALO_OFF 34816
#define SWA_HI  69632
#define SWA_LO  104448
#define SWB_HI  139264
#define SWB_LO  174080
#define SBIAS1  208896
#define SBIAS2  209408
#define SBATCH  209920
#define GEMM_SMEM 210432

__device__ __forceinline__ void mainloop_128(uint32_t sbase, uint32_t wBase,
                                             uint32_t lOff, int m0, int n0,
                                             float c[2][8][4]) {
#pragma unroll
    for (int mh = 0; mh < 2; mh++)
#pragma unroll
        for (int j = 0; j < 8; j++)
#pragma unroll
            for (int q = 0; q < 4; q++) c[mh][j][q] = 0.f;

#pragma unroll 1
    for (int ks = 0; ks < 8; ks++) {
        uint32_t ah[2][4], al[2][4];
#pragma unroll
        for (int mh = 0; mh < 2; mh++) {
            uint32_t aa = sbase + SA + (uint32_t)(m0 + mh * 16) * 272 +
                          (uint32_t)ks * 32 + lOff;
            ldsm_x4(ah[mh], aa);
            ldsm_x4(al[mh], aa + ALO_OFF);
        }
#pragma unroll
        for (int nj = 0; nj < 4; nj++) {
            uint32_t bh[4], bl[4];
            uint32_t ba = sbase + wBase + (uint32_t)ks * 16 * 272 +
                          (uint32_t)(n0 + nj * 16) * 2 + lOff;
            ldsm_x4_t(bh, ba);
            ldsm_x4_t(bl, ba + ALO_OFF);     // lo tile sits +34816 after hi
#pragma unroll
            for (int mh = 0; mh < 2; mh++) {
                mma_bf16(c[mh][2 * nj],     ah[mh], bh[0], bh[1]);
                mma_bf16(c[mh][2 * nj + 1], ah[mh], bh[2], bh[3]);
                mma_bf16(c[mh][2 * nj],     ah[mh], bl[0], bl[1]);
                mma_bf16(c[mh][2 * nj + 1], ah[mh], bl[2], bl[3]);
                mma_bf16(c[mh][2 * nj],     al[mh], bh[0], bh[1]);
                mma_bf16(c[mh][2 * nj + 1], al[mh], bh[2], bh[3]);
            }
        }
    }
}

__global__ __launch_bounds__(256, 1) void gemm_fused_kernel(
        const unsigned* __restrict__ Ahi, const unsigned* __restrict__ Alo,
        const float* __restrict__ W1a, const float* __restrict__ b1a,
        const float* __restrict__ W1b, const float* __restrict__ b1b,
        const void* __restrict__ batch, int M) {
    extern __shared__ char smem[];
    uint32_t sbase = smem_u32(smem);
    float* sBias1 = (float*)(smem + SBIAS1);
    float* sBias2 = (float*)(smem + SBIAS2);
    int* sB = (int*)(smem + SBATCH);
    int t = threadIdx.x;
    int lane = t & 31;
    int w = t >> 5;
    int wr = w >> 1, wc = w & 1;
    int m0 = wr * 32, n0 = wc * 64;
    int is64 = probe_is64(batch);

    // prologue: prefetch first tile
    {
        int tile0 = blockIdx.x;
        if (tile0 < NTILES) {
            int row0 = tile0 << 7;
            for (int idx = t; idx < 2048; idx += 256) {
                int r = idx >> 4, c4 = idx & 15;
                int gr = row0 + r;
                int ok = (gr < M) ? 16 : 0;
                int grc = ok ? gr : 0;
                cp_async16(sbase + SA + r * 272 + c4 * 16, Ahi + grc * 64 + c4 * 4, ok);
                cp_async16(sbase + SA + ALO_OFF + r * 272 + c4 * 16,
                           Alo + grc * 64 + c4 * 4, ok);
            }
        }
        CP_COMMIT();
    }

    // split both weight matrices -> smem hi/lo (overlaps prefetch)
    for (int idx = t; idx < 128 * 128; idx += 256) {
        int k = idx >> 7, n = idx & 127;
        unsigned short h, l;
        split_bf(W1a[idx], h, l);
        *(unsigned short*)(smem + SWA_HI + (k * 136 + n) * 2) = h;
        *(unsigned short*)(smem + SWA_LO + (k * 136 + n) * 2) = l;
        split_bf(W1b[idx], h, l);
        *(unsigned short*)(smem + SWB_HI + (k * 136 + n) * 2) = h;
        *(unsigned short*)(smem + SWB_LO + (k * 136 + n) * 2) = l;
    }
    if (t < 128) { sBias1[t] = b1a[t]; sBias2[t] = b1b[t]; }

    int lrow = (lane & 7) + ((lane >> 3) & 1) * 8;
    int lcol = (lane >> 4) * 8;
    uint32_t lOff = (uint32_t)(lrow * 136 + lcol) * 2;
    int er = lane >> 2;
    int ec = 2 * (lane & 3);

    for (int tile = blockIdx.x; tile < NTILES; tile += gridDim.x) {
        int row0 = tile << 7;
        CP_WAIT0();
        __syncthreads();

        float c[2][8][4];
        // ---- GEMM 1: A @ W1a ----
        mainloop_128(sbase, SWA_HI, lOff, m0, n0, c);
        __syncthreads();      // warp-pair done reading its A rows

        // epilogue 1: bias+relu, split bf16 hi/lo, write t1 back into SA
#pragma unroll
        for (int mh = 0; mh < 2; mh++)
#pragma unroll
            for (int j = 0; j < 8; j++) {
                int n = n0 + j * 8 + ec;
                float b0 = sBias1[n], b1 = sBias1[n + 1];
                float* cc = c[mh][j];
                int r0 = m0 + mh * 16 + er;
                unsigned short h0, l0, h1, l1;
                split_bf(fmaxf(cc[0] + b0, 0.f), h0, l0);
                split_bf(fmaxf(cc[1] + b1, 0.f), h1, l1);
                *(unsigned*)(smem + SA + r0 * 272 + n * 2) =
                    (unsigned)h0 | ((unsigned)h1 << 16);
                *(unsigned*)(smem + SA + ALO_OFF + r0 * 272 + n * 2) =
                    (unsigned)l0 | ((unsigned)l1 << 16);
                split_bf(fmaxf(cc[2] + b0, 0.f), h0, l0);
                split_bf(fmaxf(cc[3] + b1, 0.f), h1, l1);
                *(unsigned*)(smem + SA + (r0 + 8) * 272 + n * 2) =
                    (unsigned)h0 | ((unsigned)h1 << 16);
                *(unsigned*)(smem + SA + ALO_OFF + (r0 + 8) * 272 + n * 2) =
                    (unsigned)l0 | ((unsigned)l1 << 16);
            }
        __syncthreads();      // all t1 written

        // ---- GEMM 2: t1 @ W1b ----
        mainloop_128(sbase, SWB_HI, lOff, m0, n0, c);
        __syncthreads();      // ALL warps done reading t1 (sV overlaps rows)

        // epilogue 2: bias+relu -> fp32 sV (reuse SA region)
        float* sV = (float*)(smem + SA);
#pragma unroll
        for (int mh = 0; mh < 2; mh++)
#pragma unroll
            for (int j = 0; j < 8; j++) {
                int n = n0 + j * 8 + ec;
                int rr = m0 + mh * 16 + er;
                float b0 = sBias2[n], b1 = sBias2[n + 1];
                float* cc = c[mh][j];
                *(float2*)&sV[rr * 132 + n] =
                    make_float2(fmaxf(cc[0] + b0, 0.f), fmaxf(cc[1] + b1, 0.f));
                *(float2*)&sV[(rr + 8) * 132 + n] =
                    make_float2(fmaxf(cc[2] + b0, 0.f), fmaxf(cc[3] + b1, 0.f));
            }
        if (t < 128) {
            int gr = row0 + t;
            sB[t] = (gr < M) ? load_index(batch, gr, is64) : -1;
        }
        __syncthreads();

        // fused BN stats + per-graph pooling sums
        if (t < 128) {
            float s = 0.f, q = 0.f, run = 0.f;
            int cur = sB[0];
            for (int r = 0; r < 128; r++) {
                int b = sB[r];
                if (b != cur) {
                    if (cur >= 0) atomicAdd(&g_gsum[cur * NF + t], run);
                    run = 0.f;
                    cur = b;
                }
                if (b >= 0) {
                    float v = sV[r * 132 + t];
                    run += v;
                    s += v;
                    q += v * v;
                }
            }
            if (cur >= 0) atomicAdd(&g_gsum[cur * NF + t], run);
            atomicAdd(&g_stats[t], s);
            atomicAdd(&g_stats[128 + t], q);
        }
        __syncthreads();      // sV reads done before next prefetch overwrites

        // prefetch next tile
        {
            int nt = tile + gridDim.x;
            if (nt < NTILES) {
                int row0n = nt << 7;
                for (int idx = t; idx < 2048; idx += 256) {
                    int r = idx >> 4, c4 = idx & 15;
                    int gr = row0n + r;
                    int ok = (gr < M) ? 16 : 0;
                    int grc = ok ? gr : 0;
                    cp_async16(sbase + SA + r * 272 + c4 * 16,
                               Ahi + grc * 64 + c4 * 4, ok);
                    cp_async16(sbase + SA + ALO_OFF + r * 272 + c4 * 16,
                               Alo + grc * 64 + c4 * 4, ok);
                }
            }
            CP_COMMIT();
        }
    }
}

// ---------------- fused: BN-affine pool + recurrence + output MLP ----------
#define WT_STRIDE 260
#define RECUR_SMEM ((128 * WT_STRIDE + 128 + 4 * 256 + 96 + 8) * (int)sizeof(float))

__global__ __launch_bounds__(128) void recur_mlp_kernel(
        const void* __restrict__ batch,
        const float* __restrict__ gamma, const float* __restrict__ beta,
        const float* __restrict__ Wl1, const float* __restrict__ bl1,
        const float* __restrict__ Wl2, const float* __restrict__ bl2,
        const float* __restrict__ Wm1, const float* __restrict__ bm1,
        const float* __restrict__ Wm2, const float* __restrict__ bm2,
        float* __restrict__ out) {
    extern __shared__ float sm[];
    float* Wt  = sm;                        // [128][260]
    float* bs  = Wt + 128 * WT_STRIDE;      // [128]
    float* cat = bs + 128;                  // [4][256]
    float* hid = cat + 4 * 256;             // [96]
    int* se = (int*)(hid + 96);             // [5] + lastflag
    int t = threadIdx.x;
    int g0 = blockIdx.x * 4;
    int is64 = probe_is64(batch);

    if (t < 5) {
        int target = g0 + t;
        int lo = 0, hi = N_NODES;
        while (lo < hi) {
            int mid = (lo + hi) >> 1;
            int b = load_index(batch, mid, is64);
            if (b < target) lo = mid + 1; else hi = mid;
        }
        se[t] = lo;
    }

    for (int idx = t; idx < 256 * 64; idx += 128) {
        int k = idx >> 6, c = idx & 63;
        Wt[c * WT_STRIDE + k] = Wl2[idx];
        Wt[(c + 64) * WT_STRIDE + k] = Wl1[idx];
    }
    bs[t] = (t < 64) ? bl2[t] : bl1[t - 64];

    // read stats (then participate in ticketed zeroing)
    float st0 = g_stats[t];
    float st1 = g_stats[128 + t];
    float gs[4];
#pragma unroll
    for (int r = 0; r < 4; r++) {
        gs[r] = g_gsum[(g0 + r) * NF + t];
        g_gsum[(g0 + r) * NF + t] = 0.f;    // exclusive slice: self-clean
    }
    __syncthreads();
    if (t == 0) {
        __threadfence();
        int k = atomicAdd(&g_tickR, 1);
        se[5] = (k == N_GRAPHS / 4 - 1);
    }
    __syncthreads();
    if (se[5]) {
        g_stats[t] = 0.f;
        g_stats[128 + t] = 0.f;
        if (t == 0) g_tickR = 0;
    }

    float mu = st0 / (float)N_NODES;
    float var = st1 / (float)N_NODES - mu * mu;
    float rs = rsqrtf(var + BN_EPS);
    float gm = gamma[t], bt = beta[t];
#pragma unroll
    for (int r = 0; r < 4; r++) {
        int cnt = se[r + 1] - se[r];
        float val = 0.f;
        if (cnt > 0) {
            float m = gs[r] / (float)cnt;
            val = gm * (m - mu) * rs + bt;
        }
        cat[r * 256 + t] = val;
        cat[r * 256 + 128 + t] = val;
    }
    __syncthreads();

    const float* wv0 = &Wt[t * WT_STRIDE];
    float bias = bs[t];
    for (int it = 0; it < N_ITERS; it++) {
        float a0 = bias, a1 = bias, a2 = bias, a3 = bias;
#pragma unroll 8
        for (int k = 0; k < 256; k += 4) {
            float4 wv = *(const float4*)&wv0[k];
            float4 c0 = *(const float4*)&cat[0 * 256 + k];
            float4 c1 = *(const float4*)&cat[1 * 256 + k];
            float4 c2 = *(const float4*)&cat[2 * 256 + k];
            float4 c3 = *(const float4*)&cat[3 * 256 + k];
            a0 += c0.x * wv.x + c0.y * wv.y + c0.z * wv.z + c0.w * wv.w;
            a1 += c1.x * wv.x + c1.y * wv.y + c1.z * wv.z + c1.w * wv.w;
            a2 += c2.x * wv.x + c2.y * wv.y + c2.z * wv.z + c2.w * wv.w;
            a3 += c3.x * wv.x + c3.y * wv.y + c3.z * wv.z + c3.w * wv.w;
        }
        float o[4] = {a0, a1, a2, a3};
        float v[4];
#pragma unroll
        for (int r = 0; r < 4; r++)
            v[r] = (t < 64) ? tanhf(o[r]) : (1.0f / (1.0f + expf(-o[r])));
        __syncthreads();
#pragma unroll
        for (int r = 0; r < 4; r++) cat[r * 256 + 128 + t] = v[r];
        __syncthreads();
    }

    for (int r = 0; r < 4; r++) {
        if (t < DIM) {
            float a = bm1[t];
            const float* h = &cat[r * 256 + 128];
#pragma unroll 8
            for (int k = 0; k < NF; k++) a += h[k] * Wm1[k * DIM + t];
            hid[t] = fmaxf(a, 0.f);
        }
        __syncthreads();
        if (t < N_OUT) {
            float a = bm2[t];
            for (int k = 0; k < DIM; k++) a += hid[k] * Wm2[k * N_OUT + t];
            out[(g0 + r) * N_OUT + t] = a;
        }
        __syncthreads();
    }
}

// ---------------- host ----------------
extern "C" void kernel_launch(void* const* d_in, const int* in_sizes, int n_in,
                              void* d_out, int out_size) {
    const float* x     = (const float*)d_in[0];
    const void*  ei    = d_in[1];
    const void*  batch = d_in[2];
    const float* W1a = (const float*)d_in[3];
    const float* b1a = (const float*)d_in[4];
    const float* W1b = (const float*)d_in[5];
    const float* b1b = (const float*)d_in[6];
    const float* gamma = (const float*)d_in[7];
    const float* beta  = (const float*)d_in[8];
    const float* Wl1 = (const float*)d_in[9];
    const float* bl1 = (const float*)d_in[10];
    const float* Wl2 = (const float*)d_in[11];
    const float* bl2 = (const float*)d_in[12];
    const float* Wm1 = (const float*)d_in[13];
    const float* bm1 = (const float*)d_in[14];
    const float* Wm2 = (const float*)d_in[15];
    const float* bm2 = (const float*)d_in[16];
    float* out = (float*)d_out;

    void *p_ahi, *p_alo;
    cudaGetSymbolAddress(&p_ahi, g_ahi);
    cudaGetSymbolAddress(&p_alo, g_alo);

    cudaFuncSetAttribute(gemm_fused_kernel,
                         cudaFuncAttributeMaxDynamicSharedMemorySize, GEMM_SMEM);
    cudaFuncSetAttribute(recur_mlp_kernel,
                         cudaFuncAttributeMaxDynamicSharedMemorySize, RECUR_SMEM);

    count_kernel<<<512, 256>>>(ei);
    scanAB_kernel<<<SCAN_NBLK, 256>>>();
    scatter_kernel<<<512, 256>>>(ei);
    agg_kernel<<<(N_NODES + 7) / 8, 256>>>((const float4*)x);
    gemm_fused_kernel<<<148, 256, GEMM_SMEM>>>(
        (const unsigned*)p_ahi, (const unsigned*)p_alo,
        W1a, b1a, W1b, b1b, batch, N_NODES);
    recur_mlp_kernel<<<N_GRAPHS / 4, 128, RECUR_SMEM>>>(
        batch, gamma, beta, Wl1, bl1, Wl2, bl2, Wm1, bm1, Wm2, bm2, out);
}